// round 1
// baseline (speedup 1.0000x reference)
#include <cuda_runtime.h>
#include <cuda_bf16.h>
#include <cstdint>

#define T_      4
#define B_      32
#define N_      256
#define C_      384
#define H_      8
#define D_      48
#define BNROWS  8192            // B_*N_
#define TBN     32768           // T_*B_*N_
#define SCALE_  0.051031036307982884f   // 384^-0.5

// ---------------- scratch ----------------
__device__ float g_sq[TBN * C_];    // q spikes  [T,B,N,C]
__device__ float g_sk[TBN * C_];    // k spikes
__device__ float g_sv[TBN * C_];    // v spikes
__device__ float g_attn[TBN * C_];  // attention output (pre attn_lif)
__device__ float g_aspk[TBN * C_];  // attn_lif spikes

// ---------------- fused GEMM (Y = X @ W^T) + BN + LIF-over-T ----------------
// Block: 64 rows (16 (b,n) pairs x 4 timesteps) x 64 output channels.
// Row mapping: local row i -> bn = bn0 + (i>>2), t = i&3, global row = t*8192+bn.
// Each thread's 4-row microtile = the 4 timesteps of one (b,n): LIF in registers.
__global__ __launch_bounds__(256) void gemm_bn_lif(
    const float* __restrict__ X, const float* __restrict__ W,
    const float* __restrict__ bnp, float* __restrict__ Out)
{
    __shared__ float As[64][32];   // [row][kk]
    __shared__ float Bs[32][68];   // [kk][col], padded pitch 68

    const int bn0 = blockIdx.y * 16;
    const int c0  = blockIdx.x * 64;
    const int tid = threadIdx.x;
    const int tx  = tid & 15;      // col group
    const int ty  = tid >> 4;      // bn within tile

    float acc[4][4];
    #pragma unroll
    for (int j = 0; j < 4; ++j)
        #pragma unroll
        for (int c = 0; c < 4; ++c) acc[j][c] = 0.f;

    for (int k0 = 0; k0 < C_; k0 += 32) {
        // load A tile (coalesced 128B per row-group)
        #pragma unroll
        for (int p = 0; p < 8; ++p) {
            int e  = tid + p * 256;
            int i  = e >> 5, kk = e & 31;
            int bn = bn0 + (i >> 2), t = i & 3;
            As[i][kk] = X[(size_t)(t * BNROWS + bn) * C_ + k0 + kk];
        }
        // load B tile: Bs[kk][col] = W[c0+col][k0+kk]  (coalesced along k)
        #pragma unroll
        for (int p = 0; p < 8; ++p) {
            int kk  = tid & 31;
            int col = (tid >> 5) + p * 8;
            Bs[kk][col] = W[(size_t)(c0 + col) * C_ + k0 + kk];
        }
        __syncthreads();
        #pragma unroll
        for (int kk = 0; kk < 32; ++kk) {
            float a0 = As[ty * 4 + 0][kk];
            float a1 = As[ty * 4 + 1][kk];
            float a2 = As[ty * 4 + 2][kk];
            float a3 = As[ty * 4 + 3][kk];
            float4 b = *(const float4*)&Bs[kk][tx * 4];
            acc[0][0] += a0 * b.x; acc[0][1] += a0 * b.y; acc[0][2] += a0 * b.z; acc[0][3] += a0 * b.w;
            acc[1][0] += a1 * b.x; acc[1][1] += a1 * b.y; acc[1][2] += a1 * b.z; acc[1][3] += a1 * b.w;
            acc[2][0] += a2 * b.x; acc[2][1] += a2 * b.y; acc[2][2] += a2 * b.z; acc[2][3] += a2 * b.w;
            acc[3][0] += a3 * b.x; acc[3][1] += a3 * b.y; acc[3][2] += a3 * b.z; acc[3][3] += a3 * b.w;
        }
        __syncthreads();
    }

    // epilogue: BN (eval) then LIF over the 4 timesteps
    const int bn = bn0 + ty;
    #pragma unroll
    for (int c = 0; c < 4; ++c) {
        int cout = c0 + tx * 4 + c;
        float gamma = bnp[cout];
        float beta  = bnp[C_ + cout];
        float mean  = bnp[2 * C_ + cout];
        float var   = bnp[3 * C_ + cout];
        float sc = gamma * (1.0f / sqrtf(var + 1e-5f));
        float v = 0.f;
        #pragma unroll
        for (int t = 0; t < 4; ++t) {
            float y = (acc[t][c] - mean) * sc + beta;
            float h = v + (y - v) * 0.5f;          // tau = 2
            bool  s = (h >= 1.0f);
            Out[(size_t)(t * BNROWS + bn) * C_ + cout] = s ? 1.0f : 0.0f;
            v = s ? 0.0f : h;
        }
    }
}

// ---------------- attention: per (t,b,h) block ----------------
// scores[n][m] = popcount(qmask[n] & kmask[m]) + rel_table[n-m+255][h]
// out[n][d]    = SCALE * sum_m scores[n][m] * v[m][d]
__global__ __launch_bounds__(256) void attn_kernel(
    const float* __restrict__ Sq, const float* __restrict__ Sk,
    const float* __restrict__ Sv, const float* __restrict__ rel,
    float* __restrict__ AOut)
{
    extern __shared__ float smem[];
    float* stage  = smem;                       // 256*48 floats (staging q/k, then v)
    uint2* qm     = (uint2*)(smem + 256 * 48);  // 256 masks
    uint2* km     = qm + 256;                   // 256 masks
    float* bias_s = (float*)(km + 256);         // 511 floats

    const int bx = blockIdx.x;                  // ((t*32+b)*8+h)
    const int h  = bx & 7;
    const int b  = (bx >> 3) & 31;
    const int t  = bx >> 8;
    const int r0 = t * BNROWS + b * N_;         // first global row
    const int tid = threadIdx.x;

    // ---- stage q, pack masks ----
    for (int e = tid; e < 256 * 12; e += 256) {
        int n = e / 12, di = e % 12;
        ((float4*)stage)[e] =
            *(const float4*)(Sq + (size_t)(r0 + n) * C_ + h * D_ + di * 4);
    }
    __syncthreads();
    {
        int n = tid;
        unsigned lo = 0, hi = 0;
        #pragma unroll
        for (int d = 0; d < 32; ++d) lo |= (stage[n * 48 + d] > 0.5f) ? (1u << d) : 0u;
        #pragma unroll
        for (int d = 32; d < 48; ++d) hi |= (stage[n * 48 + d] > 0.5f) ? (1u << (d - 32)) : 0u;
        qm[n] = make_uint2(lo, hi);
    }
    __syncthreads();
    // ---- stage k, pack masks ----
    for (int e = tid; e < 256 * 12; e += 256) {
        int n = e / 12, di = e % 12;
        ((float4*)stage)[e] =
            *(const float4*)(Sk + (size_t)(r0 + n) * C_ + h * D_ + di * 4);
    }
    __syncthreads();
    {
        int n = tid;
        unsigned lo = 0, hi = 0;
        #pragma unroll
        for (int d = 0; d < 32; ++d) lo |= (stage[n * 48 + d] > 0.5f) ? (1u << d) : 0u;
        #pragma unroll
        for (int d = 32; d < 48; ++d) hi |= (stage[n * 48 + d] > 0.5f) ? (1u << (d - 32)) : 0u;
        km[n] = make_uint2(lo, hi);
    }
    __syncthreads();
    // ---- stage v (persists) + bias column ----
    for (int e = tid; e < 256 * 12; e += 256) {
        int n = e / 12, di = e % 12;
        ((float4*)stage)[e] =
            *(const float4*)(Sv + (size_t)(r0 + n) * C_ + h * D_ + di * 4);
    }
    for (int j = tid; j < 2 * N_ - 1; j += 256) bias_s[j] = rel[j * H_ + h];
    __syncthreads();

    // ---- compute: one thread per query row n ----
    const int n = tid;
    const unsigned qlo = qm[n].x, qhi = qm[n].y;
    const float* bshift = bias_s + 255 + n;     // bias_s[n-m+255] = bshift[-m]
    float out[48];
    #pragma unroll
    for (int d = 0; d < 48; ++d) out[d] = 0.f;

    for (int m = 0; m < N_; ++m) {
        uint2 k2 = km[m];
        float sc = (float)(__popc(qlo & k2.x) + __popc(qhi & k2.y)) + bshift[-m];
        const float4* vr = (const float4*)(stage + m * 48);
        #pragma unroll
        for (int dq = 0; dq < 12; ++dq) {
            float4 vv = vr[dq];
            out[dq * 4 + 0] += sc * vv.x;
            out[dq * 4 + 1] += sc * vv.y;
            out[dq * 4 + 2] += sc * vv.z;
            out[dq * 4 + 3] += sc * vv.w;
        }
    }

    float* dst = AOut + (size_t)(r0 + n) * C_ + h * D_;
    #pragma unroll
    for (int dq = 0; dq < 12; ++dq) {
        float4 o;
        o.x = out[dq * 4 + 0] * SCALE_;
        o.y = out[dq * 4 + 1] * SCALE_;
        o.z = out[dq * 4 + 2] * SCALE_;
        o.w = out[dq * 4 + 3] * SCALE_;
        *(float4*)(dst + dq * 4) = o;
    }
}

// ---------------- LIF over T (attn_lif) ----------------
__global__ __launch_bounds__(256) void lif4_kernel(
    const float* __restrict__ In, float* __restrict__ Out)
{
    int i = blockIdx.x * blockDim.x + threadIdx.x;
    if (i >= BNROWS * C_) return;
    float v = 0.f;
    #pragma unroll
    for (int t = 0; t < 4; ++t) {
        float x = In[(size_t)t * BNROWS * C_ + i];
        float hh = v + (x - v) * 0.5f;
        bool  s = (hh >= 1.0f);
        Out[(size_t)t * BNROWS * C_ + i] = s ? 1.0f : 0.0f;
        v = s ? 0.0f : hh;
    }
}

// ---------------- launch ----------------
extern "C" void kernel_launch(void* const* d_in, const int* in_sizes, int n_in,
                              void* d_out, int out_size)
{
    const float* x    = (const float*)d_in[0];
    const float* w_q  = (const float*)d_in[1];
    const float* w_k  = (const float*)d_in[2];
    const float* w_v  = (const float*)d_in[3];
    const float* w_p  = (const float*)d_in[4];
    const float* bn_q = (const float*)d_in[5];
    const float* bn_k = (const float*)d_in[6];
    const float* bn_v = (const float*)d_in[7];
    const float* bn_p = (const float*)d_in[8];
    const float* rel  = (const float*)d_in[9];
    float* out = (float*)d_out;

    float *sq, *sk, *sv, *attn, *aspk;
    cudaGetSymbolAddress((void**)&sq,   g_sq);
    cudaGetSymbolAddress((void**)&sk,   g_sk);
    cudaGetSymbolAddress((void**)&sv,   g_sv);
    cudaGetSymbolAddress((void**)&attn, g_attn);
    cudaGetSymbolAddress((void**)&aspk, g_aspk);

    cudaFuncSetAttribute(attn_kernel,
                         cudaFuncAttributeMaxDynamicSharedMemorySize, 56 * 1024);

    dim3 ggrid(C_ / 64, BNROWS / 16);   // (6, 512)
    gemm_bn_lif<<<ggrid, 256>>>(x, w_q, bn_q, sq);
    gemm_bn_lif<<<ggrid, 256>>>(x, w_k, bn_k, sk);
    gemm_bn_lif<<<ggrid, 256>>>(x, w_v, bn_v, sv);

    attn_kernel<<<T_ * B_ * H_, 256, 56 * 1024>>>(sq, sk, sv, rel, attn);

    lif4_kernel<<<(BNROWS * C_ + 255) / 256, 256>>>(attn, aspk);

    gemm_bn_lif<<<ggrid, 256>>>(aspk, w_p, bn_p, out);
}

// round 4
// speedup vs baseline: 1.2722x; 1.2722x over previous
#include <cuda_runtime.h>
#include <cuda_bf16.h>
#include <cstdint>

#define T_      4
#define B_      32
#define N_      256
#define C_      384
#define H_      8
#define D_      48
#define BNROWS  8192
#define TBN     32768
#define NELEM   (TBN * C_)            // 12582912
#define SCALE_  0.051031036307982884f // 384^-0.5

// ---------------- scratch ----------------
__device__ uint4 g_x1_[NELEM / 8];        // bf16 x splits
__device__ uint4 g_x2_[NELEM / 8];
__device__ uint4 g_x3_[NELEM / 8];
__device__ uint4 g_w1_[4 * C_ * C_ / 8];  // bf16 weight splits (q,k,v,p)
__device__ uint4 g_w2_[4 * C_ * C_ / 8];
__device__ uint4 g_w3_[4 * C_ * C_ / 8];
__device__ uint4 g_Yq_[NELEM / 4];        // fp32 GEMM outputs
__device__ uint4 g_Yk_[NELEM / 4];
__device__ uint4 g_Yv_[NELEM / 4];
__device__ uint4 g_sv_[NELEM / 4];        // fp32 v spikes
__device__ uint4 g_attn_[NELEM / 4];      // fp32 attn out (pre lif)
__device__ uint4 g_aspk_[NELEM / 8];      // bf16 attn spikes (proj input)
__device__ unsigned long long g_Qm_[TBN * 8];
__device__ unsigned long long g_Km_[TBN * 8];

// ---------------- helpers ----------------
__device__ __forceinline__ uint32_t smem_u32(const void* p) {
    uint32_t a;
    asm("{ .reg .u64 t; cvta.to.shared.u64 t, %1; cvt.u32.u64 %0, t; }"
        : "=r"(a) : "l"(p));
    return a;
}

__device__ __forceinline__ void cp_async16(uint32_t saddr, const void* gaddr) {
    asm volatile("cp.async.cg.shared.global [%0], [%1], 16;"
                 :: "r"(saddr), "l"(gaddr));
}
__device__ __forceinline__ void cp_commit() {
    asm volatile("cp.async.commit_group;");
}

__device__ __forceinline__ void ldsm_x4(uint32_t addr, uint32_t& r0, uint32_t& r1,
                                        uint32_t& r2, uint32_t& r3) {
    asm volatile("ldmatrix.sync.aligned.m8n8.x4.shared.b16 {%0,%1,%2,%3}, [%4];"
                 : "=r"(r0), "=r"(r1), "=r"(r2), "=r"(r3) : "r"(addr));
}

__device__ __forceinline__ void mma_bf16(float& c0, float& c1, float& c2, float& c3,
                                         uint32_t a0, uint32_t a1, uint32_t a2, uint32_t a3,
                                         uint32_t b0, uint32_t b1) {
    asm volatile("mma.sync.aligned.m16n8k16.row.col.f32.bf16.bf16.f32 "
                 "{%0,%1,%2,%3}, {%4,%5,%6,%7}, {%8,%9}, {%0,%1,%2,%3};"
                 : "+f"(c0), "+f"(c1), "+f"(c2), "+f"(c3)
                 : "r"(a0), "r"(a1), "r"(a2), "r"(a3), "r"(b0), "r"(b1));
}

struct GArgs {
    const __nv_bfloat16* A[3];     // A splits
    const __nv_bfloat16* W[3][3];  // [branch][split]
    float* Y[3];                   // [branch]
};

__device__ __constant__ int PA6[6] = {0, 0, 1, 1, 0, 2};
__device__ __constant__ int PB6[6] = {0, 1, 0, 1, 2, 0};

// ---------------- HMMA GEMM: Y[m][c] = sum_p sum_k Ap[m][k] * Wp[c][k] ----------------
// CTA tile 128x128, BK=32, cp.async double buffer, smem pitch 40 elems (80B, conflict-free).
template<int NPROD>
__global__ __launch_bounds__(256) void hmma_gemm(GArgs args)
{
    __shared__ __align__(128) char sh[40960]; // [buf][A 10240 | B 10240]
    const uint32_t sbase = smem_u32(sh);
    const int tid = threadIdx.x, wid = tid >> 5, l = tid & 31;
    const int wm = wid >> 2, wn = wid & 3;            // 2 x 4 warp grid
    const int m0 = blockIdx.x * 128;
    const int branch = blockIdx.y / 3;
    const int c0 = (blockIdx.y % 3) * 128;
    const int NSTEPS = NPROD * 12;

    float acc[4][4][4];
    #pragma unroll
    for (int mt = 0; mt < 4; ++mt)
        #pragma unroll
        for (int nt = 0; nt < 4; ++nt)
            #pragma unroll
            for (int r = 0; r < 4; ++r) acc[mt][nt][r] = 0.f;

    // prefetch lambda-ish
    auto prefetch = [&](int s, int buf) {
        int p = s / 12, kc = (s % 12) * 32;
        const __nv_bfloat16* Aptr = args.A[PA6[p]];
        const __nv_bfloat16* Bptr = args.W[branch][PB6[p]];
        #pragma unroll
        for (int it = 0; it < 4; ++it) {
            int idx = tid + it * 256;          // [0,1024)
            int isB = idx >> 9;
            int row = (idx >> 2) & 127;
            int ch  = idx & 3;
            const __nv_bfloat16* src = isB
                ? Bptr + (size_t)(c0 + row) * C_ + kc + ch * 8
                : Aptr + (size_t)(m0 + row) * C_ + kc + ch * 8;
            uint32_t dst = sbase + buf * 20480 + isB * 10240 + row * 80 + ch * 16;
            cp_async16(dst, src);
        }
        cp_commit();
    };

    prefetch(0, 0);

    for (int s = 0; s < NSTEPS; ++s) {
        const int buf = s & 1;
        if (s + 1 < NSTEPS) {
            prefetch(s + 1, buf ^ 1);
            asm volatile("cp.async.wait_group 1;");
        } else {
            asm volatile("cp.async.wait_group 0;");
        }
        __syncthreads();

        const uint32_t sA = sbase + buf * 20480;
        const uint32_t sB = sA + 10240;
        #pragma unroll
        for (int kk = 0; kk < 32; kk += 16) {
            uint32_t a[4][4], b[2][4];
            #pragma unroll
            for (int mt = 0; mt < 4; ++mt) {
                uint32_t addr = sA + (uint32_t)(wm * 64 + mt * 16 + (l & 15)) * 80
                              + (uint32_t)(kk + (l >> 4) * 8) * 2;
                ldsm_x4(addr, a[mt][0], a[mt][1], a[mt][2], a[mt][3]);
            }
            #pragma unroll
            for (int bt = 0; bt < 2; ++bt) {
                uint32_t nrow = wn * 32 + bt * 16 + (l & 7) + ((l >> 4) << 3);
                uint32_t addr = sB + nrow * 80
                              + (uint32_t)(kk + ((l >> 3) & 1) * 8) * 2;
                ldsm_x4(addr, b[bt][0], b[bt][1], b[bt][2], b[bt][3]);
            }
            #pragma unroll
            for (int mt = 0; mt < 4; ++mt)
                #pragma unroll
                for (int nt = 0; nt < 4; ++nt) {
                    uint32_t b0 = b[nt >> 1][(nt & 1) * 2 + 0];
                    uint32_t b1 = b[nt >> 1][(nt & 1) * 2 + 1];
                    mma_bf16(acc[mt][nt][0], acc[mt][nt][1], acc[mt][nt][2], acc[mt][nt][3],
                             a[mt][0], a[mt][1], a[mt][2], a[mt][3], b0, b1);
                }
        }
        __syncthreads();
    }

    // epilogue: direct fp32 stores
    float* Y = args.Y[branch];
    #pragma unroll
    for (int mt = 0; mt < 4; ++mt) {
        int row_lo = m0 + wm * 64 + mt * 16 + (l >> 2);
        #pragma unroll
        for (int nt = 0; nt < 4; ++nt) {
            int col = c0 + wn * 32 + nt * 8 + (l & 3) * 2;
            float2 v0 = make_float2(acc[mt][nt][0], acc[mt][nt][1]);
            float2 v1 = make_float2(acc[mt][nt][2], acc[mt][nt][3]);
            *(float2*)(Y + (size_t)row_lo * C_ + col) = v0;
            *(float2*)(Y + (size_t)(row_lo + 8) * C_ + col) = v1;
        }
    }
}

// ---------------- split fp32 into 3 bf16 terms ----------------
__global__ __launch_bounds__(256) void convert3(
    const float* __restrict__ src, __nv_bfloat16* __restrict__ d1,
    __nv_bfloat16* __restrict__ d2, __nv_bfloat16* __restrict__ d3, int n)
{
    int i = blockIdx.x * 256 + threadIdx.x;
    if (i >= n) return;
    float x = src[i];
    __nv_bfloat16 b1 = __float2bfloat16(x);
    float r1 = x - __bfloat162float(b1);
    __nv_bfloat16 b2 = __float2bfloat16(r1);
    float r2 = r1 - __bfloat162float(b2);
    __nv_bfloat16 b3 = __float2bfloat16(r2);
    d1[i] = b1; d2[i] = b2; d3[i] = b3;
}

// ---------------- BN + LIF -> packed 64-bit masks (q, k) ----------------
__global__ __launch_bounds__(384) void bn_lif_mask(
    const float* __restrict__ Y, const float* __restrict__ bnp,
    unsigned long long* __restrict__ Mout)
{
    __shared__ unsigned char bits[4][C_];
    const int bn = blockIdx.x;
    const int c  = threadIdx.x;
    float gamma = bnp[c], beta = bnp[C_ + c], mean = bnp[2 * C_ + c], var = bnp[3 * C_ + c];
    float sc = gamma * (1.0f / sqrtf(var + 1e-5f));
    float v = 0.f;
    #pragma unroll
    for (int t = 0; t < 4; ++t) {
        float y = (Y[(size_t)(t * BNROWS + bn) * C_ + c] - mean) * sc + beta;
        float h = v + (y - v) * 0.5f;
        bool s = (h >= 1.0f);
        bits[t][c] = s;
        v = s ? 0.f : h;
    }
    __syncthreads();
    if (c < 32) {
        int t = c >> 3, h = c & 7;
        unsigned long long m = 0;
        #pragma unroll
        for (int d = 0; d < 48; ++d)
            m |= bits[t][h * 48 + d] ? (1ull << d) : 0ull;
        Mout[(size_t)(t * BNROWS + bn) * 8 + h] = m;
    }
}

// ---------------- BN + LIF -> fp32 spikes ----------------
__global__ __launch_bounds__(256) void bn_lif_f32(
    const float* __restrict__ Y, const float* __restrict__ bnp, float* __restrict__ S)
{
    int i = blockIdx.x * 256 + threadIdx.x;
    if (i >= BNROWS * C_) return;
    int c = i % C_;
    float gamma = bnp[c], beta = bnp[C_ + c], mean = bnp[2 * C_ + c], var = bnp[3 * C_ + c];
    float sc = gamma * (1.0f / sqrtf(var + 1e-5f));
    float v = 0.f;
    #pragma unroll
    for (int t = 0; t < 4; ++t) {
        float y = (Y[(size_t)t * BNROWS * C_ + i] - mean) * sc + beta;
        float h = v + (y - v) * 0.5f;
        bool s = (h >= 1.0f);
        S[(size_t)t * BNROWS * C_ + i] = s ? 1.0f : 0.0f;
        v = s ? 0.f : h;
    }
}

// ---------------- LIF over T -> bf16 spikes (attn_lif, proj input) ----------------
__global__ __launch_bounds__(256) void attn_lif_pack(
    const float* __restrict__ In, __nv_bfloat16* __restrict__ Out)
{
    int i = blockIdx.x * 256 + threadIdx.x;
    if (i >= BNROWS * C_) return;
    const __nv_bfloat16 one = __float2bfloat16(1.0f);
    const __nv_bfloat16 zero = __float2bfloat16(0.0f);
    float v = 0.f;
    #pragma unroll
    for (int t = 0; t < 4; ++t) {
        float x = In[(size_t)t * BNROWS * C_ + i];
        float h = v + (x - v) * 0.5f;
        bool s = (h >= 1.0f);
        Out[(size_t)t * BNROWS * C_ + i] = s ? one : zero;
        v = s ? 0.f : h;
    }
}

// ---------------- attention: per (t,b,h) block, 64-bit popcount scores ----------------
__global__ __launch_bounds__(256) void attn_kernel(
    const unsigned long long* __restrict__ Qm, const unsigned long long* __restrict__ Km,
    const float* __restrict__ Sv, const float* __restrict__ rel, float* __restrict__ AOut)
{
    extern __shared__ char smem_raw[];
    float* vstage = (float*)smem_raw;                                  // 256*48 floats
    unsigned long long* km = (unsigned long long*)(vstage + 256 * 48); // 256
    float* bias_s = (float*)(km + 256);                                // 511

    const int bx = blockIdx.x;
    const int h = bx & 7;
    const int b = (bx >> 3) & 31;
    const int t = bx >> 8;
    const int r0 = t * BNROWS + b * N_;
    const int tid = threadIdx.x;

    for (int e = tid; e < 256 * 12; e += 256) {
        int n = e / 12, di = e % 12;
        ((float4*)vstage)[e] =
            *(const float4*)(Sv + (size_t)(r0 + n) * C_ + h * D_ + di * 4);
    }
    km[tid] = Km[(size_t)(r0 + tid) * 8 + h];
    const unsigned long long qm = Qm[(size_t)(r0 + tid) * 8 + h];
    for (int j = tid; j < 2 * N_ - 1; j += 256) bias_s[j] = rel[j * H_ + h];
    __syncthreads();

    const int n = tid;
    const float* bshift = bias_s + 255 + n;
    float out[48];
    #pragma unroll
    for (int d = 0; d < 48; ++d) out[d] = 0.f;

    for (int m = 0; m < N_; ++m) {
        float sc = (float)__popcll(qm & km[m]) + bshift[-m];
        const float4* vr = (const float4*)(vstage + m * 48);
        #pragma unroll
        for (int dq = 0; dq < 12; ++dq) {
            float4 vv = vr[dq];
            out[dq * 4 + 0] += sc * vv.x;
            out[dq * 4 + 1] += sc * vv.y;
            out[dq * 4 + 2] += sc * vv.z;
            out[dq * 4 + 3] += sc * vv.w;
        }
    }

    float* dst = AOut + (size_t)(r0 + n) * C_ + h * D_;
    #pragma unroll
    for (int dq = 0; dq < 12; ++dq) {
        float4 o;
        o.x = out[dq * 4 + 0] * SCALE_;
        o.y = out[dq * 4 + 1] * SCALE_;
        o.z = out[dq * 4 + 2] * SCALE_;
        o.w = out[dq * 4 + 3] * SCALE_;
        *(float4*)(dst + dq * 4) = o;
    }
}

// ---------------- launch ----------------
extern "C" void kernel_launch(void* const* d_in, const int* in_sizes, int n_in,
                              void* d_out, int out_size)
{
    const float* x    = (const float*)d_in[0];
    const float* w_q  = (const float*)d_in[1];
    const float* w_k  = (const float*)d_in[2];
    const float* w_v  = (const float*)d_in[3];
    const float* w_p  = (const float*)d_in[4];
    const float* bn_q = (const float*)d_in[5];
    const float* bn_k = (const float*)d_in[6];
    const float* bn_v = (const float*)d_in[7];
    const float* bn_p = (const float*)d_in[8];
    const float* rel  = (const float*)d_in[9];
    float* out = (float*)d_out;

    __nv_bfloat16 *x1, *x2, *x3, *w1, *w2, *w3, *aspk;
    float *Yq, *Yk, *Yv, *sv, *attn;
    unsigned long long *Qm, *Km;
    cudaGetSymbolAddress((void**)&x1, g_x1_);
    cudaGetSymbolAddress((void**)&x2, g_x2_);
    cudaGetSymbolAddress((void**)&x3, g_x3_);
    cudaGetSymbolAddress((void**)&w1, g_w1_);
    cudaGetSymbolAddress((void**)&w2, g_w2_);
    cudaGetSymbolAddress((void**)&w3, g_w3_);
    cudaGetSymbolAddress((void**)&Yq, g_Yq_);
    cudaGetSymbolAddress((void**)&Yk, g_Yk_);
    cudaGetSymbolAddress((void**)&Yv, g_Yv_);
    cudaGetSymbolAddress((void**)&sv, g_sv_);
    cudaGetSymbolAddress((void**)&attn, g_attn_);
    cudaGetSymbolAddress((void**)&aspk, g_aspk_);
    cudaGetSymbolAddress((void**)&Qm, g_Qm_);
    cudaGetSymbolAddress((void**)&Km, g_Km_);

    cudaFuncSetAttribute(attn_kernel,
                         cudaFuncAttributeMaxDynamicSharedMemorySize, 56 * 1024);

    const int WW = C_ * C_;

    // splits
    convert3<<<(NELEM + 255) / 256, 256>>>(x, x1, x2, x3, NELEM);
    convert3<<<(WW + 255) / 256, 256>>>(w_q, w1 + 0 * WW, w2 + 0 * WW, w3 + 0 * WW, WW);
    convert3<<<(WW + 255) / 256, 256>>>(w_k, w1 + 1 * WW, w2 + 1 * WW, w3 + 1 * WW, WW);
    convert3<<<(WW + 255) / 256, 256>>>(w_v, w1 + 2 * WW, w2 + 2 * WW, w3 + 2 * WW, WW);
    convert3<<<(WW + 255) / 256, 256>>>(w_p, w1 + 3 * WW, w2 + 3 * WW, w3 + 3 * WW, WW);

    // QKV fused GEMM (3 branches x 3 N-tiles)
    GArgs ga;
    ga.A[0] = x1; ga.A[1] = x2; ga.A[2] = x3;
    ga.W[0][0] = w1 + 0 * WW; ga.W[0][1] = w2 + 0 * WW; ga.W[0][2] = w3 + 0 * WW;
    ga.W[1][0] = w1 + 1 * WW; ga.W[1][1] = w2 + 1 * WW; ga.W[1][2] = w3 + 1 * WW;
    ga.W[2][0] = w1 + 2 * WW; ga.W[2][1] = w2 + 2 * WW; ga.W[2][2] = w3 + 2 * WW;
    ga.Y[0] = Yq; ga.Y[1] = Yk; ga.Y[2] = Yv;
    hmma_gemm<6><<<dim3(TBN / 128, 9), 256>>>(ga);

    bn_lif_mask<<<BNROWS, 384>>>(Yq, bn_q, Qm);
    bn_lif_mask<<<BNROWS, 384>>>(Yk, bn_k, Km);
    bn_lif_f32<<<(BNROWS * C_ + 255) / 256, 256>>>(Yv, bn_v, sv);

    attn_kernel<<<T_ * B_ * H_, 256, 56 * 1024>>>(Qm, Km, sv, rel, attn);

    attn_lif_pack<<<(BNROWS * C_ + 255) / 256, 256>>>(attn, aspk);

    // proj GEMM: binary A exact in bf16 -> 3 products
    GArgs gp;
    gp.A[0] = aspk; gp.A[1] = aspk; gp.A[2] = aspk;
    gp.W[0][0] = w1 + 3 * WW; gp.W[0][1] = w2 + 3 * WW; gp.W[0][2] = w3 + 3 * WW;
    gp.W[1][0] = gp.W[0][0]; gp.W[1][1] = gp.W[0][1]; gp.W[1][2] = gp.W[0][2];
    gp.W[2][0] = gp.W[0][0]; gp.W[2][1] = gp.W[0][1]; gp.W[2][2] = gp.W[0][2];
    gp.Y[0] = Yq; gp.Y[1] = Yq; gp.Y[2] = Yq;
    hmma_gemm<3><<<dim3(TBN / 128, 3), 256>>>(gp);

    bn_lif_f32<<<(BNROWS * C_ + 255) / 256, 256>>>(Yq, bn_p, out);
}

// round 5
// speedup vs baseline: 1.6793x; 1.3200x over previous
#include <cuda_runtime.h>
#include <cuda_bf16.h>
#include <cstdint>

#define T_      4
#define B_      32
#define N_      256
#define C_      384
#define H_      8
#define D_      48
#define BNROWS  8192
#define TBN     32768
#define NELEM   (TBN * C_)            // 12582912
#define SCALE_  0.051031036307982884f // 384^-0.5

// ---------------- scratch ----------------
__device__ uint4 g_x1_[NELEM / 8];        // bf16 x splits
__device__ uint4 g_x2_[NELEM / 8];
__device__ uint4 g_x3_[NELEM / 8];
__device__ uint4 g_w1_[4 * C_ * C_ / 8];  // bf16 weight splits (q,k,v,p)
__device__ uint4 g_w2_[4 * C_ * C_ / 8];
__device__ uint4 g_w3_[4 * C_ * C_ / 8];
__device__ uint4 g_spkq_[NELEM / 16];     // u8 q spikes
__device__ uint4 g_spkk_[NELEM / 16];     // u8 k spikes
__device__ uint4 g_sv_[NELEM / 4];        // f32 v spikes
__device__ uint4 g_attn_[NELEM / 4];      // f32 attn out (pre lif)
__device__ uint4 g_aspk_[NELEM / 8];      // bf16 attn spikes (proj input)
__device__ unsigned long long g_Qm_[TBN * 8];
__device__ unsigned long long g_Km_[TBN * 8];

// ---------------- helpers ----------------
__device__ __forceinline__ uint32_t smem_u32(const void* p) {
    uint32_t a;
    asm("{ .reg .u64 t; cvta.to.shared.u64 t, %1; cvt.u32.u64 %0, t; }"
        : "=r"(a) : "l"(p));
    return a;
}
__device__ __forceinline__ void cp_async16(uint32_t saddr, const void* gaddr) {
    asm volatile("cp.async.cg.shared.global [%0], [%1], 16;" :: "r"(saddr), "l"(gaddr));
}
__device__ __forceinline__ void cp_commit() { asm volatile("cp.async.commit_group;"); }

__device__ __forceinline__ void ldsm_x4(uint32_t addr, uint32_t& r0, uint32_t& r1,
                                        uint32_t& r2, uint32_t& r3) {
    asm volatile("ldmatrix.sync.aligned.m8n8.x4.shared.b16 {%0,%1,%2,%3}, [%4];"
                 : "=r"(r0), "=r"(r1), "=r"(r2), "=r"(r3) : "r"(addr));
}
__device__ __forceinline__ void mma_bf16(float& c0, float& c1, float& c2, float& c3,
                                         uint32_t a0, uint32_t a1, uint32_t a2, uint32_t a3,
                                         uint32_t b0, uint32_t b1) {
    asm volatile("mma.sync.aligned.m16n8k16.row.col.f32.bf16.bf16.f32 "
                 "{%0,%1,%2,%3}, {%4,%5,%6,%7}, {%8,%9}, {%0,%1,%2,%3};"
                 : "+f"(c0), "+f"(c1), "+f"(c2), "+f"(c3)
                 : "r"(a0), "r"(a1), "r"(a2), "r"(a3), "r"(b0), "r"(b1));
}

#define SWZB(byteoff) ((byteoff) ^ (((byteoff) >> 3) & 0x70))

struct GArgs {
    const __nv_bfloat16* A[3];     // A splits
    const __nv_bfloat16* W[3][3];  // [branch][split]
    const float* bnp[3];           // BN params per branch
    void* dst[3];                  // u8* or float* per branch
    int u8flag[3];                 // 1 -> u8 spikes, 0 -> f32 spikes
};

__device__ __constant__ int cPA6[6] = {0, 0, 1, 1, 0, 2};
__device__ __constant__ int cPB6[6] = {0, 1, 0, 1, 2, 0};
__device__ __constant__ int cPA3[3] = {0, 0, 0};
__device__ __constant__ int cPB3[3] = {0, 1, 2};

// ---------------- HMMA GEMM + fused BN/LIF epilogue ----------------
// CTA: 128 threads, 4 warps (2x2), warp tile 64x64, CTA tile 128x128, BK=64,
// 3-stage cp.async, SW128 swizzle. CTA rows are (bn,t)-interleaved: global
// row r = m0+i maps to bn = r>>2, t = r&3, so LIF-over-T happens in epilogue.
#define SSTG 32768
template<int NPROD>
__global__ __launch_bounds__(128) void hmma_gemm(GArgs args)
{
    extern __shared__ char smem_raw[];
    const uint32_t sbase = smem_u32(smem_raw);
    const int tid = threadIdx.x, wid = tid >> 5, l = tid & 31;
    const int wm = wid >> 1, wn = wid & 1;            // 2 x 2 warps
    const int m0 = blockIdx.x * 128;
    const int branch = blockIdx.y / 3;
    const int c0 = (blockIdx.y % 3) * 128;
    const int NSTEPS = NPROD * 6;

    float acc[4][8][4];
    #pragma unroll
    for (int mt = 0; mt < 4; ++mt)
        #pragma unroll
        for (int nt = 0; nt < 8; ++nt)
            #pragma unroll
            for (int r = 0; r < 4; ++r) acc[mt][nt][r] = 0.f;

    auto prefetch = [&](int s, int buf) {
        int p = (NPROD == 6) ? cPA6[s / 6] : cPA3[s / 6];
        int q = (NPROD == 6) ? cPB6[s / 6] : cPB3[s / 6];
        int kc = (s % 6) * 64;
        const __nv_bfloat16* Asrc = args.A[p];
        const __nv_bfloat16* Bsrc = args.W[branch][q];
        #pragma unroll
        for (int it = 0; it < 8; ++it) {
            int idx = tid + it * 128;           // [0,1024)
            int row = idx >> 3, ch = idx & 7;
            int r = m0 + row;
            const __nv_bfloat16* src = Asrc
                + (size_t)((r & 3) * BNROWS + (r >> 2)) * C_ + kc + ch * 8;
            uint32_t dst = sbase + buf * SSTG + SWZB((uint32_t)(row * 128 + ch * 16));
            cp_async16(dst, src);
        }
        #pragma unroll
        for (int it = 0; it < 8; ++it) {
            int idx = tid + it * 128;
            int row = idx >> 3, ch = idx & 7;
            const __nv_bfloat16* src = Bsrc
                + (size_t)(c0 + row) * C_ + kc + ch * 8;
            uint32_t dst = sbase + buf * SSTG + 16384
                         + SWZB((uint32_t)(row * 128 + ch * 16));
            cp_async16(dst, src);
        }
        cp_commit();
    };

    prefetch(0, 0);
    prefetch(1, 1);

    for (int s = 0; s < NSTEPS; ++s) {
        asm volatile("cp.async.wait_group 1;");
        __syncthreads();
        if (s + 2 < NSTEPS) prefetch(s + 2, (s + 2) % 3);

        const uint32_t sA = sbase + (s % 3) * SSTG;
        const uint32_t sB = sA + 16384;
        #pragma unroll
        for (int kk = 0; kk < 64; kk += 16) {
            uint32_t a[4][4], b[4][4];
            #pragma unroll
            for (int mt = 0; mt < 4; ++mt) {
                uint32_t row = wm * 64 + mt * 16 + (l & 15);
                uint32_t byte = row * 128 + (uint32_t)(kk + (l >> 4) * 8) * 2;
                ldsm_x4(sA + SWZB(byte), a[mt][0], a[mt][1], a[mt][2], a[mt][3]);
            }
            #pragma unroll
            for (int bt = 0; bt < 4; ++bt) {
                uint32_t nrow = wn * 64 + bt * 16 + (l & 7) + ((l >> 4) << 3);
                uint32_t byte = nrow * 128 + (uint32_t)(kk + ((l >> 3) & 1) * 8) * 2;
                ldsm_x4(sB + SWZB(byte), b[bt][0], b[bt][1], b[bt][2], b[bt][3]);
            }
            #pragma unroll
            for (int mt = 0; mt < 4; ++mt)
                #pragma unroll
                for (int nt = 0; nt < 8; ++nt) {
                    uint32_t b0 = b[nt >> 1][(nt & 1) * 2 + 0];
                    uint32_t b1 = b[nt >> 1][(nt & 1) * 2 + 1];
                    mma_bf16(acc[mt][nt][0], acc[mt][nt][1], acc[mt][nt][2], acc[mt][nt][3],
                             a[mt][0], a[mt][1], a[mt][2], a[mt][3], b0, b1);
                }
        }
        __syncthreads();
    }

    // ---- epilogue: transpose to smem [col][row] (pitch 132), BN + LIF ----
    float* eps = (float*)smem_raw;
    #pragma unroll
    for (int mt = 0; mt < 4; ++mt) {
        int r0r = wm * 64 + mt * 16 + (l >> 2);
        #pragma unroll
        for (int nt = 0; nt < 8; ++nt) {
            int cc = wn * 64 + nt * 8 + (l & 3) * 2;
            eps[(cc + 0) * 132 + r0r]     = acc[mt][nt][0];
            eps[(cc + 1) * 132 + r0r]     = acc[mt][nt][1];
            eps[(cc + 0) * 132 + r0r + 8] = acc[mt][nt][2];
            eps[(cc + 1) * 132 + r0r + 8] = acc[mt][nt][3];
        }
    }
    __syncthreads();

    {
        const int c = tid;                  // 0..127
        const int cg = c0 + c;
        const float* bnp = args.bnp[branch];
        const float gamma = bnp[cg], beta = bnp[C_ + cg];
        const float mean = bnp[2 * C_ + cg], var = bnp[3 * C_ + cg];
        const float sc = gamma * (1.0f / sqrtf(var + 1e-5f));
        const int bn0 = m0 >> 2;
        const int isU8 = args.u8flag[branch];
        uint8_t* d8 = (uint8_t*)args.dst[branch];
        float* df = (float*)args.dst[branch];
        for (int b = 0; b < 32; ++b) {
            float4 y4 = *(float4*)&eps[c * 132 + 4 * b];
            float ys[4] = {y4.x, y4.y, y4.z, y4.w};
            const int bn = bn0 + b;
            float v = 0.f;
            #pragma unroll
            for (int t = 0; t < 4; ++t) {
                float y = (ys[t] - mean) * sc + beta;
                float h = v + (y - v) * 0.5f;
                bool s = (h >= 1.0f);
                size_t o = (size_t)(t * BNROWS + bn) * C_ + cg;
                if (isU8) d8[o] = s ? 1 : 0;
                else      df[o] = s ? 1.0f : 0.0f;
                v = s ? 0.f : h;
            }
        }
    }
}

// ---------------- split fp32 into 3 bf16 terms ----------------
__global__ __launch_bounds__(256) void convert3(
    const float* __restrict__ src, __nv_bfloat16* __restrict__ d1,
    __nv_bfloat16* __restrict__ d2, __nv_bfloat16* __restrict__ d3, int n)
{
    int i = blockIdx.x * 256 + threadIdx.x;
    if (i >= n) return;
    float x = src[i];
    __nv_bfloat16 b1 = __float2bfloat16(x);
    float r1 = x - __bfloat162float(b1);
    __nv_bfloat16 b2 = __float2bfloat16(r1);
    float r2 = r1 - __bfloat162float(b2);
    __nv_bfloat16 b3 = __float2bfloat16(r2);
    d1[i] = b1; d2[i] = b2; d3[i] = b3;
}

// ---------------- pack u8 spikes -> 64-bit masks per head ----------------
__global__ __launch_bounds__(256) void pack_mask(
    const uint8_t* __restrict__ S, unsigned long long* __restrict__ M)
{
    int i = blockIdx.x * 256 + threadIdx.x;   // (row, h)
    if (i >= TBN * 8) return;
    int row = i >> 3, h = i & 7;
    const uint8_t* p = S + (size_t)row * C_ + h * D_;
    unsigned long long m = 0;
    #pragma unroll
    for (int d = 0; d < 48; ++d) m |= p[d] ? (1ull << d) : 0ull;
    M[i] = m;
}

// ---------------- LIF over T -> bf16 spikes (attn_lif, proj input) ----------------
__global__ __launch_bounds__(256) void attn_lif_pack(
    const float* __restrict__ In, __nv_bfloat16* __restrict__ Out)
{
    int i = blockIdx.x * 256 + threadIdx.x;
    if (i >= BNROWS * C_) return;
    const __nv_bfloat16 one = __float2bfloat16(1.0f);
    const __nv_bfloat16 zero = __float2bfloat16(0.0f);
    float v = 0.f;
    #pragma unroll
    for (int t = 0; t < 4; ++t) {
        float x = In[(size_t)t * BNROWS * C_ + i];
        float h = v + (x - v) * 0.5f;
        bool s = (h >= 1.0f);
        Out[(size_t)t * BNROWS * C_ + i] = s ? one : zero;
        v = s ? 0.f : h;
    }
}

// ---------------- attention: per (t,b,h) block, 64-bit popcount scores ----------------
__global__ __launch_bounds__(256) void attn_kernel(
    const unsigned long long* __restrict__ Qm, const unsigned long long* __restrict__ Km,
    const float* __restrict__ Sv, const float* __restrict__ rel, float* __restrict__ AOut)
{
    extern __shared__ char smem_raw[];
    float* vstage = (float*)smem_raw;                                  // 256*48 floats
    unsigned long long* km = (unsigned long long*)(vstage + 256 * 48); // 256
    float* bias_s = (float*)(km + 256);                                // 511

    const int bx = blockIdx.x;
    const int h = bx & 7;
    const int b = (bx >> 3) & 31;
    const int t = bx >> 8;
    const int r0 = t * BNROWS + b * N_;
    const int tid = threadIdx.x;

    for (int e = tid; e < 256 * 12; e += 256) {
        int n = e / 12, di = e % 12;
        ((float4*)vstage)[e] =
            *(const float4*)(Sv + (size_t)(r0 + n) * C_ + h * D_ + di * 4);
    }
    km[tid] = Km[(size_t)(r0 + tid) * 8 + h];
    const unsigned long long qm = Qm[(size_t)(r0 + tid) * 8 + h];
    for (int j = tid; j < 2 * N_ - 1; j += 256) bias_s[j] = rel[j * H_ + h];
    __syncthreads();

    const int n = tid;
    const float* bshift = bias_s + 255 + n;
    float out[48];
    #pragma unroll
    for (int d = 0; d < 48; ++d) out[d] = 0.f;

    for (int m = 0; m < N_; ++m) {
        float sc = (float)__popcll(qm & km[m]) + bshift[-m];
        const float4* vr = (const float4*)(vstage + m * 48);
        #pragma unroll
        for (int dq = 0; dq < 12; ++dq) {
            float4 vv = vr[dq];
            out[dq * 4 + 0] += sc * vv.x;
            out[dq * 4 + 1] += sc * vv.y;
            out[dq * 4 + 2] += sc * vv.z;
            out[dq * 4 + 3] += sc * vv.w;
        }
    }

    float* dst = AOut + (size_t)(r0 + n) * C_ + h * D_;
    #pragma unroll
    for (int dq = 0; dq < 12; ++dq) {
        float4 o;
        o.x = out[dq * 4 + 0] * SCALE_;
        o.y = out[dq * 4 + 1] * SCALE_;
        o.z = out[dq * 4 + 2] * SCALE_;
        o.w = out[dq * 4 + 3] * SCALE_;
        *(float4*)(dst + dq * 4) = o;
    }
}

// ---------------- launch ----------------
extern "C" void kernel_launch(void* const* d_in, const int* in_sizes, int n_in,
                              void* d_out, int out_size)
{
    const float* x    = (const float*)d_in[0];
    const float* w_q  = (const float*)d_in[1];
    const float* w_k  = (const float*)d_in[2];
    const float* w_v  = (const float*)d_in[3];
    const float* w_p  = (const float*)d_in[4];
    const float* bn_q = (const float*)d_in[5];
    const float* bn_k = (const float*)d_in[6];
    const float* bn_v = (const float*)d_in[7];
    const float* bn_p = (const float*)d_in[8];
    const float* rel  = (const float*)d_in[9];
    float* out = (float*)d_out;

    __nv_bfloat16 *x1, *x2, *x3, *w1, *w2, *w3, *aspk;
    uint8_t *spkq, *spkk;
    float *sv, *attn;
    unsigned long long *Qm, *Km;
    cudaGetSymbolAddress((void**)&x1, g_x1_);
    cudaGetSymbolAddress((void**)&x2, g_x2_);
    cudaGetSymbolAddress((void**)&x3, g_x3_);
    cudaGetSymbolAddress((void**)&w1, g_w1_);
    cudaGetSymbolAddress((void**)&w2, g_w2_);
    cudaGetSymbolAddress((void**)&w3, g_w3_);
    cudaGetSymbolAddress((void**)&spkq, g_spkq_);
    cudaGetSymbolAddress((void**)&spkk, g_spkk_);
    cudaGetSymbolAddress((void**)&sv, g_sv_);
    cudaGetSymbolAddress((void**)&attn, g_attn_);
    cudaGetSymbolAddress((void**)&aspk, g_aspk_);
    cudaGetSymbolAddress((void**)&Qm, g_Qm_);
    cudaGetSymbolAddress((void**)&Km, g_Km_);

    const int GSMEM = 3 * SSTG;   // 98304
    cudaFuncSetAttribute(hmma_gemm<6>, cudaFuncAttributeMaxDynamicSharedMemorySize, GSMEM);
    cudaFuncSetAttribute(hmma_gemm<3>, cudaFuncAttributeMaxDynamicSharedMemorySize, GSMEM);
    cudaFuncSetAttribute(attn_kernel,  cudaFuncAttributeMaxDynamicSharedMemorySize, 56 * 1024);

    const int WW = C_ * C_;

    convert3<<<(NELEM + 255) / 256, 256>>>(x, x1, x2, x3, NELEM);
    convert3<<<(WW + 255) / 256, 256>>>(w_q, w1 + 0 * WW, w2 + 0 * WW, w3 + 0 * WW, WW);
    convert3<<<(WW + 255) / 256, 256>>>(w_k, w1 + 1 * WW, w2 + 1 * WW, w3 + 1 * WW, WW);
    convert3<<<(WW + 255) / 256, 256>>>(w_v, w1 + 2 * WW, w2 + 2 * WW, w3 + 2 * WW, WW);
    convert3<<<(WW + 255) / 256, 256>>>(w_p, w1 + 3 * WW, w2 + 3 * WW, w3 + 3 * WW, WW);

    // fused QKV GEMM + BN + LIF (q,k -> u8 spikes; v -> f32 spikes)
    GArgs ga;
    ga.A[0] = x1; ga.A[1] = x2; ga.A[2] = x3;
    ga.W[0][0] = w1 + 0 * WW; ga.W[0][1] = w2 + 0 * WW; ga.W[0][2] = w3 + 0 * WW;
    ga.W[1][0] = w1 + 1 * WW; ga.W[1][1] = w2 + 1 * WW; ga.W[1][2] = w3 + 1 * WW;
    ga.W[2][0] = w1 + 2 * WW; ga.W[2][1] = w2 + 2 * WW; ga.W[2][2] = w3 + 2 * WW;
    ga.bnp[0] = bn_q; ga.bnp[1] = bn_k; ga.bnp[2] = bn_v;
    ga.dst[0] = spkq; ga.dst[1] = spkk; ga.dst[2] = sv;
    ga.u8flag[0] = 1; ga.u8flag[1] = 1; ga.u8flag[2] = 0;
    hmma_gemm<6><<<dim3(TBN / 128, 9), 128, GSMEM>>>(ga);

    pack_mask<<<(TBN * 8 + 255) / 256, 256>>>(spkq, Qm);
    pack_mask<<<(TBN * 8 + 255) / 256, 256>>>(spkk, Km);

    attn_kernel<<<T_ * B_ * H_, 256, 56 * 1024>>>(Qm, Km, sv, rel, attn);

    attn_lif_pack<<<(BNROWS * C_ + 255) / 256, 256>>>(attn, aspk);

    // proj GEMM (binary A exact in bf16 -> 3 products) writes final spikes
    GArgs gp;
    gp.A[0] = aspk; gp.A[1] = aspk; gp.A[2] = aspk;
    gp.W[0][0] = w1 + 3 * WW; gp.W[0][1] = w2 + 3 * WW; gp.W[0][2] = w3 + 3 * WW;
    gp.W[1][0] = gp.W[0][0]; gp.W[1][1] = gp.W[0][1]; gp.W[1][2] = gp.W[0][2];
    gp.W[2][0] = gp.W[0][0]; gp.W[2][1] = gp.W[0][1]; gp.W[2][2] = gp.W[0][2];
    gp.bnp[0] = bn_p; gp.bnp[1] = bn_p; gp.bnp[2] = bn_p;
    gp.dst[0] = out; gp.dst[1] = out; gp.dst[2] = out;
    gp.u8flag[0] = 0; gp.u8flag[1] = 0; gp.u8flag[2] = 0;
    hmma_gemm<3><<<dim3(TBN / 128, 3), 128, GSMEM>>>(gp);
}

// round 7
// speedup vs baseline: 1.9975x; 1.1895x over previous
#include <cuda_runtime.h>
#include <cuda_bf16.h>
#include <cstdint>

#define T_      4
#define B_      32
#define N_      256
#define C_      384
#define H_      8
#define D_      48
#define BNROWS  8192
#define TBN     32768
#define NELEM   (TBN * C_)            // 12582912
#define SCALE_  0.051031036307982884f // 384^-0.5

// ---------------- scratch ----------------
__device__ uint4 g_x1_[NELEM / 8];        // bf16 x splits
__device__ uint4 g_x2_[NELEM / 8];
__device__ uint4 g_x3_[NELEM / 8];
__device__ uint4 g_w1_[4 * C_ * C_ / 8];  // bf16 weight splits (q,k,v,p)
__device__ uint4 g_w2_[4 * C_ * C_ / 8];
__device__ uint4 g_w3_[4 * C_ * C_ / 8];
__device__ uint4 g_spkq_[NELEM / 16];     // u8 q spikes
__device__ uint4 g_spkk_[NELEM / 16];     // u8 k spikes
__device__ uint4 g_svb_[NELEM / 8];       // bf16 v spikes
__device__ uint4 g_attn_[NELEM / 4];      // f32 attn out (pre lif)
__device__ uint4 g_aspk_[NELEM / 8];      // bf16 attn spikes (proj input)
__device__ uint4 g_bm1_[8 * 256 * 256 / 8]; // bf16 bias split 1 [h][n][m]
__device__ uint4 g_bm2_[8 * 256 * 256 / 8]; // bf16 bias split 2
__device__ unsigned long long g_Qm_[TBN * 8];
__device__ unsigned long long g_Km_[TBN * 8];

// ---------------- helpers ----------------
__device__ __forceinline__ uint32_t smem_u32(const void* p) {
    uint32_t a;
    asm("{ .reg .u64 t; cvta.to.shared.u64 t, %1; cvt.u32.u64 %0, t; }"
        : "=r"(a) : "l"(p));
    return a;
}
__device__ __forceinline__ void cp_async16(uint32_t saddr, const void* gaddr) {
    asm volatile("cp.async.cg.shared.global [%0], [%1], 16;" :: "r"(saddr), "l"(gaddr));
}
__device__ __forceinline__ void cp_commit() { asm volatile("cp.async.commit_group;"); }

__device__ __forceinline__ void ldsm_x4(uint32_t addr, uint32_t& r0, uint32_t& r1,
                                        uint32_t& r2, uint32_t& r3) {
    asm volatile("ldmatrix.sync.aligned.m8n8.x4.shared.b16 {%0,%1,%2,%3}, [%4];"
                 : "=r"(r0), "=r"(r1), "=r"(r2), "=r"(r3) : "r"(addr));
}
__device__ __forceinline__ void mma_bf16(float& c0, float& c1, float& c2, float& c3,
                                         uint32_t a0, uint32_t a1, uint32_t a2, uint32_t a3,
                                         uint32_t b0, uint32_t b1) {
    asm volatile("mma.sync.aligned.m16n8k16.row.col.f32.bf16.bf16.f32 "
                 "{%0,%1,%2,%3}, {%4,%5,%6,%7}, {%8,%9}, {%0,%1,%2,%3};"
                 : "+f"(c0), "+f"(c1), "+f"(c2), "+f"(c3)
                 : "r"(a0), "r"(a1), "r"(a2), "r"(a3), "r"(b0), "r"(b1));
}

#define SWZ128(o) ((o) ^ (((o) >> 3) & 0x70))

struct GArgs {
    const __nv_bfloat16* A[3];     // A splits
    const __nv_bfloat16* W[3][3];  // [branch][split]
    const float* bnp[3];           // BN params per branch
    void* dst[3];                  // output per branch
    int mode[3];                   // 0=f32 spikes, 1=u8 spikes, 2=bf16 spikes
};

// ---------------- HMMA GEMM, kc-outer, fused BN/LIF ----------------
// 256 thr (8 warps 2x4, warp tile 64x32), CTA tile 128x128, BK=32.
// Stage = 6 tensors x 8KB (SW64 swizzle, 64B rows), double-buffered (96KB), 2 CTA/SM.
#define GSTG 49152
template<int NPROD>
__global__ __launch_bounds__(256) void hmma_gemm(GArgs args)
{
    extern __shared__ char smem_raw[];
    const uint32_t sbase = smem_u32(smem_raw);
    const int tid = threadIdx.x, wid = tid >> 5, l = tid & 31;
    const int wm = wid >> 2, wn = wid & 3;
    const int m0 = blockIdx.x * 128;
    const int branch = blockIdx.y / 3;
    const int c0 = (blockIdx.y % 3) * 128;

    float acc[4][4][4];
    #pragma unroll
    for (int mt = 0; mt < 4; ++mt)
        #pragma unroll
        for (int nt = 0; nt < 4; ++nt)
            #pragma unroll
            for (int r = 0; r < 4; ++r) acc[mt][nt][r] = 0.f;

    auto prefetch = [&](int kc, int buf) {
        #pragma unroll
        for (int t = 0; t < 6; ++t) {
            if (NPROD == 3 && (t == 1 || t == 2)) continue;
            const __nv_bfloat16* g = (t < 3) ? args.A[t] : args.W[branch][t - 3];
            #pragma unroll
            for (int it = 0; it < 2; ++it) {
                int idx = tid + it * 256;     // 512 granules per tensor
                int row = idx >> 2, ch = idx & 3;
                const __nv_bfloat16* src;
                if (t < 3) {
                    int r = m0 + row;
                    src = g + (size_t)((r & 3) * BNROWS + (r >> 2)) * C_ + kc * 32 + ch * 8;
                } else {
                    src = g + (size_t)(c0 + row) * C_ + kc * 32 + ch * 8;
                }
                uint32_t dst = sbase + buf * GSTG + t * 8192
                             + row * 64 + ((ch * 16) ^ ((row & 6) << 3));
                cp_async16(dst, src);
            }
        }
        cp_commit();
    };

    prefetch(0, 0);
    prefetch(1, 1);

    for (int s = 0; s < 12; ++s) {
        if (s < 11) asm volatile("cp.async.wait_group 1;");
        else        asm volatile("cp.async.wait_group 0;");
        __syncthreads();

        const uint32_t sb = sbase + (s & 1) * GSTG;
        #pragma unroll
        for (int kk = 0; kk < 2; ++kk) {
            #pragma unroll
            for (int pa = 0; pa < 3; ++pa) {
                if (NPROD == 3 && pa > 0) break;
                uint32_t a[4][4];
                #pragma unroll
                for (int mt = 0; mt < 4; ++mt) {
                    uint32_t row = wm * 64 + mt * 16 + (l & 15);
                    uint32_t ko = (uint32_t)(kk * 16 + (l >> 4) * 8) * 2;
                    ldsm_x4(sb + pa * 8192 + row * 64 + (ko ^ ((row & 6) << 3)),
                            a[mt][0], a[mt][1], a[mt][2], a[mt][3]);
                }
                #pragma unroll
                for (int pb = 0; pb < 3; ++pb) {
                    bool use = (NPROD == 3) ? true : (pa + pb <= 2);
                    if (!use) continue;
                    uint32_t b[2][4];
                    #pragma unroll
                    for (int bt = 0; bt < 2; ++bt) {
                        uint32_t nrow = wn * 32 + bt * 16 + (l & 7) + ((l >> 4) << 3);
                        uint32_t ko = (uint32_t)(kk * 16 + ((l >> 3) & 1) * 8) * 2;
                        ldsm_x4(sb + (3 + pb) * 8192 + nrow * 64 + (ko ^ ((nrow & 6) << 3)),
                                b[bt][0], b[bt][1], b[bt][2], b[bt][3]);
                    }
                    #pragma unroll
                    for (int mt = 0; mt < 4; ++mt)
                        #pragma unroll
                        for (int nt = 0; nt < 4; ++nt) {
                            uint32_t b0 = b[nt >> 1][(nt & 1) * 2 + 0];
                            uint32_t b1 = b[nt >> 1][(nt & 1) * 2 + 1];
                            mma_bf16(acc[mt][nt][0], acc[mt][nt][1],
                                     acc[mt][nt][2], acc[mt][nt][3],
                                     a[mt][0], a[mt][1], a[mt][2], a[mt][3], b0, b1);
                        }
                }
            }
        }
        __syncthreads();
        if (s + 2 < 12) prefetch(s + 2, s & 1);
    }

    // ---- epilogue: transpose to smem [col][row] pitch 132, BN + LIF ----
    float* eps = (float*)smem_raw;
    #pragma unroll
    for (int mt = 0; mt < 4; ++mt) {
        int r0r = wm * 64 + mt * 16 + (l >> 2);
        #pragma unroll
        for (int nt = 0; nt < 4; ++nt) {
            int cc = wn * 32 + nt * 8 + (l & 3) * 2;
            eps[(cc + 0) * 132 + r0r]     = acc[mt][nt][0];
            eps[(cc + 1) * 132 + r0r]     = acc[mt][nt][1];
            eps[(cc + 0) * 132 + r0r + 8] = acc[mt][nt][2];
            eps[(cc + 1) * 132 + r0r + 8] = acc[mt][nt][3];
        }
    }
    __syncthreads();

    {
        const int c = tid & 127;
        const int half = tid >> 7;
        const int cg = c0 + c;
        const float* bnp = args.bnp[branch];
        const float gamma = bnp[cg], beta = bnp[C_ + cg];
        const float mean = bnp[2 * C_ + cg], var = bnp[3 * C_ + cg];
        const float sc = gamma * (1.0f / sqrtf(var + 1e-5f));
        const int bn0 = m0 >> 2;
        const int mode = args.mode[branch];
        uint8_t* d8 = (uint8_t*)args.dst[branch];
        float* df = (float*)args.dst[branch];
        __nv_bfloat16* db = (__nv_bfloat16*)args.dst[branch];
        const __nv_bfloat16 bone = __float2bfloat16(1.0f);
        const __nv_bfloat16 bzero = __float2bfloat16(0.0f);
        for (int b = 0; b < 16; ++b) {
            const int bidx = half * 16 + b;
            float4 y4 = *(float4*)&eps[c * 132 + 4 * bidx];
            float ys[4] = {y4.x, y4.y, y4.z, y4.w};
            const int bn = bn0 + bidx;
            float v = 0.f;
            #pragma unroll
            for (int t = 0; t < 4; ++t) {
                float y = (ys[t] - mean) * sc + beta;
                float h = v + (y - v) * 0.5f;
                bool s = (h >= 1.0f);
                size_t o = (size_t)(t * BNROWS + bn) * C_ + cg;
                if (mode == 1)      d8[o] = s ? 1 : 0;
                else if (mode == 2) db[o] = s ? bone : bzero;
                else                df[o] = s ? 1.0f : 0.0f;
                v = s ? 0.f : h;
            }
        }
    }
}

// ---------------- split fp32 into 3 bf16 terms ----------------
__global__ __launch_bounds__(256) void convert3(
    const float* __restrict__ src, __nv_bfloat16* __restrict__ d1,
    __nv_bfloat16* __restrict__ d2, __nv_bfloat16* __restrict__ d3, int n)
{
    int i = blockIdx.x * 256 + threadIdx.x;
    if (i >= n) return;
    float x = src[i];
    __nv_bfloat16 b1 = __float2bfloat16(x);
    float r1 = x - __bfloat162float(b1);
    __nv_bfloat16 b2 = __float2bfloat16(r1);
    float r2 = r1 - __bfloat162float(b2);
    __nv_bfloat16 b3 = __float2bfloat16(r2);
    d1[i] = b1; d2[i] = b2; d3[i] = b3;
}

// ---------------- build bf16 Toeplitz bias matrices (2-term split) ----------------
__global__ __launch_bounds__(256) void biasmat(
    const float* __restrict__ rel, __nv_bfloat16* __restrict__ bm1,
    __nv_bfloat16* __restrict__ bm2)
{
    int i = blockIdx.x * 256 + threadIdx.x;   // [h][n][m]
    if (i >= 8 * 256 * 256) return;
    int h = i >> 16, n = (i >> 8) & 255, m = i & 255;
    float r = rel[(n - m + 255) * H_ + h];
    __nv_bfloat16 b1 = __float2bfloat16(r);
    float r2 = r - __bfloat162float(b1);
    bm1[i] = b1;
    bm2[i] = __float2bfloat16(r2);
}

// ---------------- pack u8 spikes -> 64-bit masks per head ----------------
__global__ __launch_bounds__(256) void pack_mask(
    const uint8_t* __restrict__ S, unsigned long long* __restrict__ M)
{
    int i = blockIdx.x * 256 + threadIdx.x;   // (row, h)
    if (i >= TBN * 8) return;
    int row = i >> 3, h = i & 7;
    const uint8_t* p = S + (size_t)row * C_ + h * D_;
    unsigned long long m = 0;
    #pragma unroll
    for (int d = 0; d < 48; ++d) m |= p[d] ? (1ull << d) : 0ull;
    M[i] = m;
}

// ---------------- LIF over T -> bf16 spikes (attn_lif, proj input) ----------------
__global__ __launch_bounds__(256) void attn_lif_pack(
    const float* __restrict__ In, __nv_bfloat16* __restrict__ Out)
{
    int i = blockIdx.x * 256 + threadIdx.x;
    if (i >= BNROWS * C_) return;
    const __nv_bfloat16 one = __float2bfloat16(1.0f);
    const __nv_bfloat16 zero = __float2bfloat16(0.0f);
    float v = 0.f;
    #pragma unroll
    for (int t = 0; t < 4; ++t) {
        float x = In[(size_t)t * BNROWS * C_ + i];
        float h = v + (x - v) * 0.5f;
        bool s = (h >= 1.0f);
        Out[(size_t)t * BNROWS * C_ + i] = s ? one : zero;
        v = s ? 0.f : h;
    }
}

// ---------------- attention via HMMA ----------------
// Per (t,b,h) CTA, 256 thr (8 warps, warp tile 32x48).
// out[n][d] = SCALE * sum_m (Sint[n][m] + bias1[n][m] + bias2[n][m]) * V[m][d]
// 12 A-chunks [256 n x 64 m] bf16: chunks 0-7 = bias (cp.async from bmat tables),
// 8-11 = Sint (popcount, exact ints in bf16). V in smem transposed [d][m].
#define ABUF(i) (sbase + (uint32_t)(i) * 32768u)
#define VBUF    (sbase + 98304u)
__global__ __launch_bounds__(256) void attn_mma(
    const unsigned long long* __restrict__ Qm, const unsigned long long* __restrict__ Km,
    const __nv_bfloat16* __restrict__ V, const __nv_bfloat16* __restrict__ bm1,
    const __nv_bfloat16* __restrict__ bm2, float* __restrict__ AOut)
{
    extern __shared__ char smem_raw[];
    const uint32_t sbase = smem_u32(smem_raw);
    unsigned long long* qm_s = (unsigned long long*)(smem_raw + 131072);
    unsigned long long* km_s = qm_s + 256;

    const int tid = threadIdx.x, wid = tid >> 5, l = tid & 31;
    const int bx = blockIdx.x;
    const int h = bx & 7;
    const int b = (bx >> 3) & 31;
    const int t = bx >> 8;
    const int r0 = t * BNROWS + b * N_;

    auto issue_bias = [&](int c, int buf) {
        const __nv_bfloat16* bm = (c < 4) ? bm1 : bm2;
        int mc = c & 3;
        #pragma unroll
        for (int it = 0; it < 8; ++it) {
            int g = tid + it * 256;            // 2048 granules
            int n = g >> 3, ch = g & 7;
            const __nv_bfloat16* src = bm + (size_t)((h * 256 + n) * 256 + mc * 64 + ch * 8);
            cp_async16(ABUF(buf) + SWZ128((uint32_t)(n * 128 + ch * 16)), src);
        }
        cp_commit();
    };

    // pre-issue bias chunks 0, 1
    issue_bias(0, 0);
    issue_bias(1, 1);

    // masks -> smem
    qm_s[tid] = Qm[(size_t)(r0 + tid) * 8 + h];
    km_s[tid] = Km[(size_t)(r0 + tid) * 8 + h];

    // V load + transpose into [d][m] (pitch 512B, XOR swizzle)
    #pragma unroll
    for (int it = 0; it < 6; ++it) {
        int g = tid + it * 256;                // 1536 granules
        int m = g / 6, dc = g % 6;
        uint4 v = *(const uint4*)(V + (size_t)(r0 + m) * C_ + h * D_ + dc * 8);
        const unsigned short* e = (const unsigned short*)&v;
        #pragma unroll
        for (int ee = 0; ee < 8; ++ee) {
            int d = dc * 8 + ee;
            *(unsigned short*)(smem_raw + 98304 + d * 512 + ((m * 2) ^ ((d & 7) << 4))) = e[ee];
        }
    }

    float acc[2][6][4];
    #pragma unroll
    for (int mt = 0; mt < 2; ++mt)
        #pragma unroll
        for (int nt = 0; nt < 6; ++nt)
            #pragma unroll
            for (int r = 0; r < 4; ++r) acc[mt][nt][r] = 0.f;

    for (int c = 0; c < 12; ++c) {
        const int buf = c % 3;
        const int mc = c & 3;
        if (c < 8) {
            if (c + 2 < 8) issue_bias(c + 2, (c + 2) % 3);
            if (c <= 5)      asm volatile("cp.async.wait_group 2;");
            else if (c == 6) asm volatile("cp.async.wait_group 1;");
            else             asm volatile("cp.async.wait_group 0;");
        } else {
            // build Sint chunk: A[n][j] = popcll(qm[n] & km[mc*64+j]) as bf16
            #pragma unroll
            for (int it = 0; it < 8; ++it) {
                int g = tid + it * 256;
                int n = g >> 3, ch = g & 7;
                unsigned long long q = qm_s[n];
                union { unsigned short u[8]; uint4 v; } pk;
                #pragma unroll
                for (int ee = 0; ee < 8; ++ee) {
                    int m = mc * 64 + ch * 8 + ee;
                    float fs = (float)__popcll(q & km_s[m]);
                    __nv_bfloat16 hb = __float2bfloat16(fs);
                    pk.u[ee] = *reinterpret_cast<unsigned short*>(&hb);
                }
                *(uint4*)(smem_raw + buf * 32768 + SWZ128((uint32_t)(n * 128 + ch * 16))) = pk.v;
            }
        }
        __syncthreads();

        // consume chunk: K-range m = mc*64 .. +64
        #pragma unroll
        for (int kk = 0; kk < 4; ++kk) {
            uint32_t a[2][4], bfr[3][4];
            #pragma unroll
            for (int mt = 0; mt < 2; ++mt) {
                uint32_t row = wid * 32 + mt * 16 + (l & 15);
                uint32_t byte = row * 128 + (uint32_t)(kk * 16 + (l >> 4) * 8) * 2;
                ldsm_x4(ABUF(buf) + SWZ128(byte), a[mt][0], a[mt][1], a[mt][2], a[mt][3]);
            }
            #pragma unroll
            for (int bt = 0; bt < 3; ++bt) {
                uint32_t nrow = bt * 16 + (l & 7) + ((l >> 4) << 3);
                uint32_t k = mc * 64 + kk * 16 + ((l >> 3) & 1) * 8;
                uint32_t addr = VBUF + nrow * 512 + ((k * 2) ^ ((nrow & 7) << 4));
                ldsm_x4(addr, bfr[bt][0], bfr[bt][1], bfr[bt][2], bfr[bt][3]);
            }
            #pragma unroll
            for (int mt = 0; mt < 2; ++mt)
                #pragma unroll
                for (int nt = 0; nt < 6; ++nt) {
                    uint32_t b0 = bfr[nt >> 1][(nt & 1) * 2 + 0];
                    uint32_t b1 = bfr[nt >> 1][(nt & 1) * 2 + 1];
                    mma_bf16(acc[mt][nt][0], acc[mt][nt][1], acc[mt][nt][2], acc[mt][nt][3],
                             a[mt][0], a[mt][1], a[mt][2], a[mt][3], b0, b1);
                }
        }
        __syncthreads();
    }

    // epilogue: scale + store f32
    #pragma unroll
    for (int mt = 0; mt < 2; ++mt) {
        int n = wid * 32 + mt * 16 + (l >> 2);
        #pragma unroll
        for (int nt = 0; nt < 6; ++nt) {
            int d = nt * 8 + (l & 3) * 2;
            float* dst = AOut + (size_t)(r0 + n) * C_ + h * D_ + d;
            *(float2*)dst = make_float2(acc[mt][nt][0] * SCALE_, acc[mt][nt][1] * SCALE_);
            float* dst2 = dst + (size_t)8 * C_;
            *(float2*)dst2 = make_float2(acc[mt][nt][2] * SCALE_, acc[mt][nt][3] * SCALE_);
        }
    }
}

// ---------------- launch ----------------
extern "C" void kernel_launch(void* const* d_in, const int* in_sizes, int n_in,
                              void* d_out, int out_size)
{
    const float* x    = (const float*)d_in[0];
    const float* w_q  = (const float*)d_in[1];
    const float* w_k  = (const float*)d_in[2];
    const float* w_v  = (const float*)d_in[3];
    const float* w_p  = (const float*)d_in[4];
    const float* bn_q = (const float*)d_in[5];
    const float* bn_k = (const float*)d_in[6];
    const float* bn_v = (const float*)d_in[7];
    const float* bn_p = (const float*)d_in[8];
    const float* rel  = (const float*)d_in[9];
    float* out = (float*)d_out;

    __nv_bfloat16 *x1, *x2, *x3, *w1, *w2, *w3, *svb, *aspk, *bm1, *bm2;
    uint8_t *spkq, *spkk;
    float *attn;
    unsigned long long *Qm, *Km;
    cudaGetSymbolAddress((void**)&x1, g_x1_);
    cudaGetSymbolAddress((void**)&x2, g_x2_);
    cudaGetSymbolAddress((void**)&x3, g_x3_);
    cudaGetSymbolAddress((void**)&w1, g_w1_);
    cudaGetSymbolAddress((void**)&w2, g_w2_);
    cudaGetSymbolAddress((void**)&w3, g_w3_);
    cudaGetSymbolAddress((void**)&spkq, g_spkq_);
    cudaGetSymbolAddress((void**)&spkk, g_spkk_);
    cudaGetSymbolAddress((void**)&svb, g_svb_);
    cudaGetSymbolAddress((void**)&attn, g_attn_);
    cudaGetSymbolAddress((void**)&aspk, g_aspk_);
    cudaGetSymbolAddress((void**)&bm1, g_bm1_);
    cudaGetSymbolAddress((void**)&bm2, g_bm2_);
    cudaGetSymbolAddress((void**)&Qm, g_Qm_);
    cudaGetSymbolAddress((void**)&Km, g_Km_);

    const int GSMEM = 2 * GSTG;     // 98304
    const int ASMEM = 135168;       // 3*32768 + 32768 + 4096
    cudaFuncSetAttribute(hmma_gemm<6>, cudaFuncAttributeMaxDynamicSharedMemorySize, GSMEM);
    cudaFuncSetAttribute(hmma_gemm<3>, cudaFuncAttributeMaxDynamicSharedMemorySize, GSMEM);
    cudaFuncSetAttribute(attn_mma,     cudaFuncAttributeMaxDynamicSharedMemorySize, ASMEM);

    const int WW = C_ * C_;

    convert3<<<(NELEM + 255) / 256, 256>>>(x, x1, x2, x3, NELEM);
    convert3<<<(WW + 255) / 256, 256>>>(w_q, w1 + 0 * WW, w2 + 0 * WW, w3 + 0 * WW, WW);
    convert3<<<(WW + 255) / 256, 256>>>(w_k, w1 + 1 * WW, w2 + 1 * WW, w3 + 1 * WW, WW);
    convert3<<<(WW + 255) / 256, 256>>>(w_v, w1 + 2 * WW, w2 + 2 * WW, w3 + 2 * WW, WW);
    convert3<<<(WW + 255) / 256, 256>>>(w_p, w1 + 3 * WW, w2 + 3 * WW, w3 + 3 * WW, WW);
    biasmat<<<(8 * 256 * 256 + 255) / 256, 256>>>(rel, bm1, bm2);

    // fused QKV GEMM + BN + LIF (q,k -> u8; v -> bf16)
    GArgs ga;
    ga.A[0] = x1; ga.A[1] = x2; ga.A[2] = x3;
    ga.W[0][0] = w1 + 0 * WW; ga.W[0][1] = w2 + 0 * WW; ga.W[0][2] = w3 + 0 * WW;
    ga.W[1][0] = w1 + 1 * WW; ga.W[1][1] = w2 + 1 * WW; ga.W[1][2] = w3 + 1 * WW;
    ga.W[2][0] = w1 + 2 * WW; ga.W[2][1] = w2 + 2 * WW; ga.W[2][2] = w3 + 2 * WW;
    ga.bnp[0] = bn_q; ga.bnp[1] = bn_k; ga.bnp[2] = bn_v;
    ga.dst[0] = spkq; ga.dst[1] = spkk; ga.dst[2] = svb;
    ga.mode[0] = 1; ga.mode[1] = 1; ga.mode[2] = 2;
    hmma_gemm<6><<<dim3(TBN / 128, 9), 256, GSMEM>>>(ga);

    pack_mask<<<(TBN * 8 + 255) / 256, 256>>>(spkq, Qm);
    pack_mask<<<(TBN * 8 + 255) / 256, 256>>>(spkk, Km);

    attn_mma<<<T_ * B_ * H_, 256, ASMEM>>>(Qm, Km, svb, bm1, bm2, attn);

    attn_lif_pack<<<(BNROWS * C_ + 255) / 256, 256>>>(attn, aspk);

    // proj GEMM (binary A exact in bf16 -> 3 products) writes final spikes
    GArgs gp;
    gp.A[0] = aspk; gp.A[1] = aspk; gp.A[2] = aspk;
    gp.W[0][0] = w1 + 3 * WW; gp.W[0][1] = w2 + 3 * WW; gp.W[0][2] = w3 + 3 * WW;
    gp.W[1][0] = gp.W[0][0]; gp.W[1][1] = gp.W[0][1]; gp.W[1][2] = gp.W[0][2];
    gp.W[2][0] = gp.W[0][0]; gp.W[2][1] = gp.W[0][1]; gp.W[2][2] = gp.W[0][2];
    gp.bnp[0] = bn_p; gp.bnp[1] = bn_p; gp.bnp[2] = bn_p;
    gp.dst[0] = out; gp.dst[1] = out; gp.dst[2] = out;
    gp.mode[0] = 0; gp.mode[1] = 0; gp.mode[2] = 0;
    hmma_gemm<3><<<dim3(TBN / 128, 3), 256, GSMEM>>>(gp);
}

// round 9
// speedup vs baseline: 2.2469x; 1.1249x over previous
#include <cuda_runtime.h>
#include <cuda_bf16.h>
#include <cstdint>

#define T_      4
#define B_      32
#define N_      256
#define C_      384
#define H_      8
#define D_      48
#define BNROWS  8192
#define TBN     32768
#define NELEM   (TBN * C_)            // 12582912
#define SCALE_  0.051031036307982884f // 384^-0.5

// ---------------- scratch ----------------
__device__ uint4 g_x1_[NELEM / 8];        // bf16 x splits
__device__ uint4 g_x2_[NELEM / 8];
__device__ uint4 g_x3_[NELEM / 8];
__device__ uint4 g_w1_[4 * C_ * C_ / 8];  // bf16 weight splits (q,k,v,p)
__device__ uint4 g_w2_[4 * C_ * C_ / 8];
__device__ uint4 g_w3_[4 * C_ * C_ / 8];
__device__ uint4 g_sqb_[NELEM / 8];       // bf16 q spikes
__device__ uint4 g_skb_[NELEM / 8];       // bf16 k spikes
__device__ uint4 g_svb_[NELEM / 8];       // bf16 v spikes
__device__ uint4 g_attn_[NELEM / 4];      // f32 attn out (pre lif)
__device__ uint4 g_aspk_[NELEM / 8];      // bf16 attn spikes (proj input)
__device__ uint4 g_bm1_[8 * 256 * 256 / 8]; // bf16 bias split 1 [h][n][m]
__device__ uint4 g_bm2_[8 * 256 * 256 / 8]; // bf16 bias split 2

// ---------------- helpers ----------------
__device__ __forceinline__ uint32_t smem_u32(const void* p) {
    uint32_t a;
    asm("{ .reg .u64 t; cvta.to.shared.u64 t, %1; cvt.u32.u64 %0, t; }"
        : "=r"(a) : "l"(p));
    return a;
}
__device__ __forceinline__ void cp_async16(uint32_t saddr, const void* gaddr) {
    asm volatile("cp.async.cg.shared.global [%0], [%1], 16;" :: "r"(saddr), "l"(gaddr));
}
__device__ __forceinline__ void cp_commit() { asm volatile("cp.async.commit_group;"); }

__device__ __forceinline__ void ldsm_x4(uint32_t addr, uint32_t& r0, uint32_t& r1,
                                        uint32_t& r2, uint32_t& r3) {
    asm volatile("ldmatrix.sync.aligned.m8n8.x4.shared.b16 {%0,%1,%2,%3}, [%4];"
                 : "=r"(r0), "=r"(r1), "=r"(r2), "=r"(r3) : "r"(addr));
}
__device__ __forceinline__ void mma_bf16(float& c0, float& c1, float& c2, float& c3,
                                         uint32_t a0, uint32_t a1, uint32_t a2, uint32_t a3,
                                         uint32_t b0, uint32_t b1) {
    asm volatile("mma.sync.aligned.m16n8k16.row.col.f32.bf16.bf16.f32 "
                 "{%0,%1,%2,%3}, {%4,%5,%6,%7}, {%8,%9}, {%0,%1,%2,%3};"
                 : "+f"(c0), "+f"(c1), "+f"(c2), "+f"(c3)
                 : "r"(a0), "r"(a1), "r"(a2), "r"(a3), "r"(b0), "r"(b1));
}

#define SWZ128(o) ((o) ^ (((o) >> 3) & 0x70))

struct GArgs {
    const __nv_bfloat16* A[3];     // A splits
    const __nv_bfloat16* W[3][3];  // [branch][split]
    const float* bnp[3];           // BN params per branch
    void* dst[3];                  // output per branch
    int mode[3];                   // 0=f32 spikes, 2=bf16 spikes
};

// ---------------- HMMA GEMM, kc-outer, fused BN/LIF ----------------
#define GSTG 49152
template<int NPROD>
__global__ __launch_bounds__(256) void hmma_gemm(GArgs args)
{
    extern __shared__ char smem_raw[];
    const uint32_t sbase = smem_u32(smem_raw);
    const int tid = threadIdx.x, wid = tid >> 5, l = tid & 31;
    const int wm = wid >> 2, wn = wid & 3;
    const int m0 = blockIdx.x * 128;
    const int branch = blockIdx.y / 3;
    const int c0 = (blockIdx.y % 3) * 128;

    float acc[4][4][4];
    #pragma unroll
    for (int mt = 0; mt < 4; ++mt)
        #pragma unroll
        for (int nt = 0; nt < 4; ++nt)
            #pragma unroll
            for (int r = 0; r < 4; ++r) acc[mt][nt][r] = 0.f;

    auto prefetch = [&](int kc, int buf) {
        #pragma unroll
        for (int t = 0; t < 6; ++t) {
            if (NPROD == 3 && (t == 1 || t == 2)) continue;
            const __nv_bfloat16* g = (t < 3) ? args.A[t] : args.W[branch][t - 3];
            #pragma unroll
            for (int it = 0; it < 2; ++it) {
                int idx = tid + it * 256;
                int row = idx >> 2, ch = idx & 3;
                const __nv_bfloat16* src;
                if (t < 3) {
                    int r = m0 + row;
                    src = g + (size_t)((r & 3) * BNROWS + (r >> 2)) * C_ + kc * 32 + ch * 8;
                } else {
                    src = g + (size_t)(c0 + row) * C_ + kc * 32 + ch * 8;
                }
                uint32_t dst = sbase + buf * GSTG + t * 8192
                             + row * 64 + ((ch * 16) ^ ((row & 6) << 3));
                cp_async16(dst, src);
            }
        }
        cp_commit();
    };

    prefetch(0, 0);
    prefetch(1, 1);

    for (int s = 0; s < 12; ++s) {
        if (s < 11) asm volatile("cp.async.wait_group 1;");
        else        asm volatile("cp.async.wait_group 0;");
        __syncthreads();

        const uint32_t sb = sbase + (s & 1) * GSTG;
        #pragma unroll
        for (int kk = 0; kk < 2; ++kk) {
            #pragma unroll
            for (int pa = 0; pa < 3; ++pa) {
                if (NPROD == 3 && pa > 0) break;
                uint32_t a[4][4];
                #pragma unroll
                for (int mt = 0; mt < 4; ++mt) {
                    uint32_t row = wm * 64 + mt * 16 + (l & 15);
                    uint32_t ko = (uint32_t)(kk * 16 + (l >> 4) * 8) * 2;
                    ldsm_x4(sb + pa * 8192 + row * 64 + (ko ^ ((row & 6) << 3)),
                            a[mt][0], a[mt][1], a[mt][2], a[mt][3]);
                }
                #pragma unroll
                for (int pb = 0; pb < 3; ++pb) {
                    bool use = (NPROD == 3) ? true : (pa + pb <= 2);
                    if (!use) continue;
                    uint32_t b[2][4];
                    #pragma unroll
                    for (int bt = 0; bt < 2; ++bt) {
                        uint32_t nrow = wn * 32 + bt * 16 + (l & 7) + ((l >> 4) << 3);
                        uint32_t ko = (uint32_t)(kk * 16 + ((l >> 3) & 1) * 8) * 2;
                        ldsm_x4(sb + (3 + pb) * 8192 + nrow * 64 + (ko ^ ((nrow & 6) << 3)),
                                b[bt][0], b[bt][1], b[bt][2], b[bt][3]);
                    }
                    #pragma unroll
                    for (int mt = 0; mt < 4; ++mt)
                        #pragma unroll
                        for (int nt = 0; nt < 4; ++nt) {
                            uint32_t b0 = b[nt >> 1][(nt & 1) * 2 + 0];
                            uint32_t b1 = b[nt >> 1][(nt & 1) * 2 + 1];
                            mma_bf16(acc[mt][nt][0], acc[mt][nt][1],
                                     acc[mt][nt][2], acc[mt][nt][3],
                                     a[mt][0], a[mt][1], a[mt][2], a[mt][3], b0, b1);
                        }
                }
            }
        }
        __syncthreads();
        if (s + 2 < 12) prefetch(s + 2, s & 1);
    }

    // ---- epilogue: transpose to smem [col][row] pitch 132, BN + LIF ----
    float* eps = (float*)smem_raw;
    #pragma unroll
    for (int mt = 0; mt < 4; ++mt) {
        int r0r = wm * 64 + mt * 16 + (l >> 2);
        #pragma unroll
        for (int nt = 0; nt < 4; ++nt) {
            int cc = wn * 32 + nt * 8 + (l & 3) * 2;
            eps[(cc + 0) * 132 + r0r]     = acc[mt][nt][0];
            eps[(cc + 1) * 132 + r0r]     = acc[mt][nt][1];
            eps[(cc + 0) * 132 + r0r + 8] = acc[mt][nt][2];
            eps[(cc + 1) * 132 + r0r + 8] = acc[mt][nt][3];
        }
    }
    __syncthreads();

    {
        const int c = tid & 127;
        const int half = tid >> 7;
        const int cg = c0 + c;
        const float* bnp = args.bnp[branch];
        const float gamma = bnp[cg], beta = bnp[C_ + cg];
        const float mean = bnp[2 * C_ + cg], var = bnp[3 * C_ + cg];
        const float sc = gamma * (1.0f / sqrtf(var + 1e-5f));
        const int bn0 = m0 >> 2;
        const int mode = args.mode[branch];
        float* df = (float*)args.dst[branch];
        __nv_bfloat16* db = (__nv_bfloat16*)args.dst[branch];
        const __nv_bfloat16 bone = __float2bfloat16(1.0f);
        const __nv_bfloat16 bzero = __float2bfloat16(0.0f);
        for (int b = 0; b < 16; ++b) {
            const int bidx = half * 16 + b;
            float4 y4 = *(float4*)&eps[c * 132 + 4 * bidx];
            float ys[4] = {y4.x, y4.y, y4.z, y4.w};
            const int bn = bn0 + bidx;
            float v = 0.f;
            #pragma unroll
            for (int t = 0; t < 4; ++t) {
                float y = (ys[t] - mean) * sc + beta;
                float h = v + (y - v) * 0.5f;
                bool s = (h >= 1.0f);
                size_t o = (size_t)(t * BNROWS + bn) * C_ + cg;
                if (mode == 2) db[o] = s ? bone : bzero;
                else           df[o] = s ? 1.0f : 0.0f;
                v = s ? 0.f : h;
            }
        }
    }
}

// ---------------- split fp32 into 3 bf16 terms ----------------
__global__ __launch_bounds__(256) void convert3(
    const float* __restrict__ src, __nv_bfloat16* __restrict__ d1,
    __nv_bfloat16* __restrict__ d2, __nv_bfloat16* __restrict__ d3, int n)
{
    int i = blockIdx.x * 256 + threadIdx.x;
    if (i >= n) return;
    float x = src[i];
    __nv_bfloat16 b1 = __float2bfloat16(x);
    float r1 = x - __bfloat162float(b1);
    __nv_bfloat16 b2 = __float2bfloat16(r1);
    float r2 = r1 - __bfloat162float(b2);
    __nv_bfloat16 b3 = __float2bfloat16(r2);
    d1[i] = b1; d2[i] = b2; d3[i] = b3;
}

// ---------------- build bf16 Toeplitz bias matrices (2-term split) ----------------
__global__ __launch_bounds__(256) void biasmat(
    const float* __restrict__ rel, __nv_bfloat16* __restrict__ bm1,
    __nv_bfloat16* __restrict__ bm2)
{
    int i = blockIdx.x * 256 + threadIdx.x;   // [h][n][m]
    if (i >= 8 * 256 * 256) return;
    int h = i >> 16, n = (i >> 8) & 255, m = i & 255;
    float r = rel[(n - m + 255) * H_ + h];
    __nv_bfloat16 b1 = __float2bfloat16(r);
    float r2 = r - __bfloat162float(b1);
    bm1[i] = b1;
    bm2[i] = __float2bfloat16(r2);
}

// ---------------- LIF over T -> bf16 spikes (attn_lif, proj input) ----------------
__global__ __launch_bounds__(256) void attn_lif_pack(
    const float* __restrict__ In, __nv_bfloat16* __restrict__ Out)
{
    int i = blockIdx.x * 256 + threadIdx.x;
    if (i >= BNROWS * C_) return;
    const __nv_bfloat16 one = __float2bfloat16(1.0f);
    const __nv_bfloat16 zero = __float2bfloat16(0.0f);
    float v = 0.f;
    #pragma unroll
    for (int t = 0; t < 4; ++t) {
        float x = In[(size_t)t * BNROWS * C_ + i];
        float h = v + (x - v) * 0.5f;
        bool s = (h >= 1.0f);
        Out[(size_t)t * BNROWS * C_ + i] = s ? one : zero;
        v = s ? 0.f : h;
    }
}

// ---------------- attention via HMMA, factorized S-path ----------------
// out[n][d] = SCALE * ( Q[n,:]·(K^T V)[:,d] + sum_m (bias1+bias2)[n][m] V[m][d] )
// K^T V entries are integer counts <= 256: exact in bf16. Q binary. All S-path
// arithmetic exact. Bias path: 8 chunks (2 bf16 splits x 4 m-chunks of 64).
#define ABUF(i)  (sbase + (uint32_t)(i) * 32768u)
#define VTB      (sbase + 98304u)
#define KTB      (sbase + 122880u)
#define QB       (sbase + 147456u)
#define KTVB     (sbase + 180224u)
__global__ __launch_bounds__(256) void attn_mma(
    const __nv_bfloat16* __restrict__ Qs, const __nv_bfloat16* __restrict__ Ks,
    const __nv_bfloat16* __restrict__ Vs, const __nv_bfloat16* __restrict__ bm1,
    const __nv_bfloat16* __restrict__ bm2, float* __restrict__ AOut)
{
    extern __shared__ char smem_raw[];
    const uint32_t sbase = smem_u32(smem_raw);

    const int tid = threadIdx.x, wid = tid >> 5, l = tid & 31;
    const int bx = blockIdx.x;
    const int h = bx & 7;
    const int b = (bx >> 3) & 31;
    const int t = bx >> 8;
    const int r0 = t * BNROWS + b * N_;

    auto issue_bias = [&](int c, int buf) {
        const __nv_bfloat16* bm = (c < 4) ? bm1 : bm2;
        int mc = c & 3;
        #pragma unroll
        for (int it = 0; it < 8; ++it) {
            int g = tid + it * 256;            // 2048 granules
            int n = g >> 3, ch = g & 7;
            const __nv_bfloat16* src = bm + (size_t)((h * 256 + n) * 256 + mc * 64 + ch * 8);
            cp_async16(ABUF(buf) + SWZ128((uint32_t)(n * 128 + ch * 16)), src);
        }
        cp_commit();
    };

    // group 0: Q tile [256 n x 48 d'] pitch 128B
    #pragma unroll
    for (int it = 0; it < 6; ++it) {
        int g = tid + it * 256;
        int n = g / 6, ch = g % 6;
        cp_async16(QB + SWZ128((uint32_t)(n * 128 + ch * 16)),
                   Qs + (size_t)(r0 + n) * C_ + h * D_ + ch * 8);
    }
    cp_commit();
    issue_bias(0, 0);   // group 1
    issue_bias(1, 1);   // group 2

    // scalar transpose K and V into [d][m] (pitch 512B, XOR swizzle)
    #pragma unroll
    for (int src_i = 0; src_i < 2; ++src_i) {
        const __nv_bfloat16* S = src_i ? Vs : Ks;
        char* base = smem_raw + (src_i ? 98304 : 122880);
        #pragma unroll
        for (int it = 0; it < 6; ++it) {
            int g = tid + it * 256;
            int m = g / 6, dc = g % 6;
            uint4 v = *(const uint4*)(S + (size_t)(r0 + m) * C_ + h * D_ + dc * 8);
            const unsigned short* e = (const unsigned short*)&v;
            #pragma unroll
            for (int ee = 0; ee < 8; ++ee) {
                int d = dc * 8 + ee;
                *(unsigned short*)(base + d * 512 + ((m * 2) ^ ((d & 7) << 4))) = e[ee];
            }
        }
    }
    __syncthreads();

    // ---- stage 1: KTV[d'][d] = sum_m K[m][d'] V[m][d], write transposed to KTVB ----
    // 9 units (mt: d' tile of 16, dpair: d tile of 16); warp wid -> unit wid (+8 for warp 0)
    for (int u = wid; u < 9; u += 8) {
        const int mt = u / 3, dp = u % 3;
        float ka[2][4];
        #pragma unroll
        for (int q = 0; q < 2; ++q)
            #pragma unroll
            for (int r = 0; r < 4; ++r) ka[q][r] = 0.f;
        for (int kidx = 0; kidx < 16; ++kidx) {
            uint32_t a0, a1, a2, a3, b0, b1, b2, b3;
            uint32_t arow = mt * 16 + (l & 15);
            uint32_t ko = (uint32_t)(kidx * 16 + (l >> 4) * 8) * 2;
            ldsm_x4(KTB + arow * 512 + (ko ^ ((arow & 7) << 4)), a0, a1, a2, a3);
            uint32_t brow = dp * 16 + (l & 7) + ((l >> 4) << 3);
            uint32_t kb = (uint32_t)(kidx * 16 + ((l >> 3) & 1) * 8) * 2;
            ldsm_x4(VTB + brow * 512 + (kb ^ ((brow & 7) << 4)), b0, b1, b2, b3);
            mma_bf16(ka[0][0], ka[0][1], ka[0][2], ka[0][3], a0, a1, a2, a3, b0, b1);
            mma_bf16(ka[1][0], ka[1][1], ka[1][2], ka[1][3], a0, a1, a2, a3, b2, b3);
        }
        // write transposed: ktv_s[d][d'] (bf16, exact ints <= 256)
        int r = mt * 16 + (l >> 2);
        #pragma unroll
        for (int q = 0; q < 2; ++q) {
            int d = dp * 16 + q * 8 + (l & 3) * 2;
            __nv_bfloat16 v0 = __float2bfloat16(ka[q][0]);
            __nv_bfloat16 v1 = __float2bfloat16(ka[q][1]);
            __nv_bfloat16 v2 = __float2bfloat16(ka[q][2]);
            __nv_bfloat16 v3 = __float2bfloat16(ka[q][3]);
            char* kb = smem_raw + 180224;
            *(unsigned short*)(kb + SWZ128((uint32_t)((d + 0) * 128 + r * 2)))       = *(unsigned short*)&v0;
            *(unsigned short*)(kb + SWZ128((uint32_t)((d + 1) * 128 + r * 2)))       = *(unsigned short*)&v1;
            *(unsigned short*)(kb + SWZ128((uint32_t)((d + 0) * 128 + (r + 8) * 2))) = *(unsigned short*)&v2;
            *(unsigned short*)(kb + SWZ128((uint32_t)((d + 1) * 128 + (r + 8) * 2))) = *(unsigned short*)&v3;
        }
    }
    __syncthreads();

    float acc[2][6][4];
    #pragma unroll
    for (int mt = 0; mt < 2; ++mt)
        #pragma unroll
        for (int nt = 0; nt < 6; ++nt)
            #pragma unroll
            for (int r = 0; r < 4; ++r) acc[mt][nt][r] = 0.f;

    // ---- stage 2: acc += Q[n][d'] * KTV[d'][d] (k = 48, 3 steps) ----
    asm volatile("cp.async.wait_group 2;");  // Q (group 0) done
    __syncthreads();
    #pragma unroll
    for (int kk = 0; kk < 3; ++kk) {
        uint32_t a[2][4], bfr[3][4];
        #pragma unroll
        for (int mt = 0; mt < 2; ++mt) {
            uint32_t row = wid * 32 + mt * 16 + (l & 15);
            uint32_t byte = row * 128 + (uint32_t)(kk * 16 + (l >> 4) * 8) * 2;
            ldsm_x4(QB + SWZ128(byte), a[mt][0], a[mt][1], a[mt][2], a[mt][3]);
        }
        #pragma unroll
        for (int bt = 0; bt < 3; ++bt) {
            uint32_t nrow = bt * 16 + (l & 7) + ((l >> 4) << 3);
            uint32_t byte = nrow * 128 + (uint32_t)(kk * 16 + ((l >> 3) & 1) * 8) * 2;
            ldsm_x4(KTVB + SWZ128(byte), bfr[bt][0], bfr[bt][1], bfr[bt][2], bfr[bt][3]);
        }
        #pragma unroll
        for (int mt = 0; mt < 2; ++mt)
            #pragma unroll
            for (int nt = 0; nt < 6; ++nt) {
                uint32_t b0 = bfr[nt >> 1][(nt & 1) * 2 + 0];
                uint32_t b1 = bfr[nt >> 1][(nt & 1) * 2 + 1];
                mma_bf16(acc[mt][nt][0], acc[mt][nt][1], acc[mt][nt][2], acc[mt][nt][3],
                         a[mt][0], a[mt][1], a[mt][2], a[mt][3], b0, b1);
            }
    }

    // ---- bias chunks: acc += bias_chunk[n][64m] * V[m][d] ----
    for (int c = 0; c < 8; ++c) {
        const int buf = c % 3;
        const int mc = c & 3;
        if (c + 2 < 8) issue_bias(c + 2, (c + 2) % 3);
        if (c <= 5)      asm volatile("cp.async.wait_group 2;");
        else if (c == 6) asm volatile("cp.async.wait_group 1;");
        else             asm volatile("cp.async.wait_group 0;");
        __syncthreads();

        #pragma unroll
        for (int kk = 0; kk < 4; ++kk) {
            uint32_t a[2][4], bfr[3][4];
            #pragma unroll
            for (int mt = 0; mt < 2; ++mt) {
                uint32_t row = wid * 32 + mt * 16 + (l & 15);
                uint32_t byte = row * 128 + (uint32_t)(kk * 16 + (l >> 4) * 8) * 2;
                ldsm_x4(ABUF(buf) + SWZ128(byte), a[mt][0], a[mt][1], a[mt][2], a[mt][3]);
            }
            #pragma unroll
            for (int bt = 0; bt < 3; ++bt) {
                uint32_t nrow = bt * 16 + (l & 7) + ((l >> 4) << 3);
                uint32_t k = mc * 64 + kk * 16 + ((l >> 3) & 1) * 8;
                uint32_t addr = VTB + nrow * 512 + ((k * 2) ^ ((nrow & 7) << 4));
                ldsm_x4(addr, bfr[bt][0], bfr[bt][1], bfr[bt][2], bfr[bt][3]);
            }
            #pragma unroll
            for (int mt = 0; mt < 2; ++mt)
                #pragma unroll
                for (int nt = 0; nt < 6; ++nt) {
                    uint32_t b0 = bfr[nt >> 1][(nt & 1) * 2 + 0];
                    uint32_t b1 = bfr[nt >> 1][(nt & 1) * 2 + 1];
                    mma_bf16(acc[mt][nt][0], acc[mt][nt][1], acc[mt][nt][2], acc[mt][nt][3],
                             a[mt][0], a[mt][1], a[mt][2], a[mt][3], b0, b1);
                }
        }
        __syncthreads();
    }

    // epilogue: scale + store f32
    #pragma unroll
    for (int mt = 0; mt < 2; ++mt) {
        int n = wid * 32 + mt * 16 + (l >> 2);
        #pragma unroll
        for (int nt = 0; nt < 6; ++nt) {
            int d = nt * 8 + (l & 3) * 2;
            float* dst = AOut + (size_t)(r0 + n) * C_ + h * D_ + d;
            *(float2*)dst = make_float2(acc[mt][nt][0] * SCALE_, acc[mt][nt][1] * SCALE_);
            float* dst2 = dst + (size_t)8 * C_;
            *(float2*)dst2 = make_float2(acc[mt][nt][2] * SCALE_, acc[mt][nt][3] * SCALE_);
        }
    }
}

// ---------------- launch ----------------
extern "C" void kernel_launch(void* const* d_in, const int* in_sizes, int n_in,
                              void* d_out, int out_size)
{
    const float* x    = (const float*)d_in[0];
    const float* w_q  = (const float*)d_in[1];
    const float* w_k  = (const float*)d_in[2];
    const float* w_v  = (const float*)d_in[3];
    const float* w_p  = (const float*)d_in[4];
    const float* bn_q = (const float*)d_in[5];
    const float* bn_k = (const float*)d_in[6];
    const float* bn_v = (const float*)d_in[7];
    const float* bn_p = (const float*)d_in[8];
    const float* rel  = (const float*)d_in[9];
    float* out = (float*)d_out;

    __nv_bfloat16 *x1, *x2, *x3, *w1, *w2, *w3, *sqb, *skb, *svb, *aspk, *bm1, *bm2;
    float *attn;
    cudaGetSymbolAddress((void**)&x1, g_x1_);
    cudaGetSymbolAddress((void**)&x2, g_x2_);
    cudaGetSymbolAddress((void**)&x3, g_x3_);
    cudaGetSymbolAddress((void**)&w1, g_w1_);
    cudaGetSymbolAddress((void**)&w2, g_w2_);
    cudaGetSymbolAddress((void**)&w3, g_w3_);
    cudaGetSymbolAddress((void**)&sqb, g_sqb_);
    cudaGetSymbolAddress((void**)&skb, g_skb_);
    cudaGetSymbolAddress((void**)&svb, g_svb_);
    cudaGetSymbolAddress((void**)&attn, g_attn_);
    cudaGetSymbolAddress((void**)&aspk, g_aspk_);
    cudaGetSymbolAddress((void**)&bm1, g_bm1_);
    cudaGetSymbolAddress((void**)&bm2, g_bm2_);

    const int GSMEM = 2 * GSTG;     // 98304
    const int ASMEM = 186368;
    cudaFuncSetAttribute(hmma_gemm<6>, cudaFuncAttributeMaxDynamicSharedMemorySize, GSMEM);
    cudaFuncSetAttribute(hmma_gemm<3>, cudaFuncAttributeMaxDynamicSharedMemorySize, GSMEM);
    cudaFuncSetAttribute(attn_mma,     cudaFuncAttributeMaxDynamicSharedMemorySize, ASMEM);

    const int WW = C_ * C_;

    convert3<<<(NELEM + 255) / 256, 256>>>(x, x1, x2, x3, NELEM);
    convert3<<<(WW + 255) / 256, 256>>>(w_q, w1 + 0 * WW, w2 + 0 * WW, w3 + 0 * WW, WW);
    convert3<<<(WW + 255) / 256, 256>>>(w_k, w1 + 1 * WW, w2 + 1 * WW, w3 + 1 * WW, WW);
    convert3<<<(WW + 255) / 256, 256>>>(w_v, w1 + 2 * WW, w2 + 2 * WW, w3 + 2 * WW, WW);
    convert3<<<(WW + 255) / 256, 256>>>(w_p, w1 + 3 * WW, w2 + 3 * WW, w3 + 3 * WW, WW);
    biasmat<<<(8 * 256 * 256 + 255) / 256, 256>>>(rel, bm1, bm2);

    // fused QKV GEMM + BN + LIF -> bf16 spikes
    GArgs ga;
    ga.A[0] = x1; ga.A[1] = x2; ga.A[2] = x3;
    ga.W[0][0] = w1 + 0 * WW; ga.W[0][1] = w2 + 0 * WW; ga.W[0][2] = w3 + 0 * WW;
    ga.W[1][0] = w1 + 1 * WW; ga.W[1][1] = w2 + 1 * WW; ga.W[1][2] = w3 + 1 * WW;
    ga.W[2][0] = w1 + 2 * WW; ga.W[2][1] = w2 + 2 * WW; ga.W[2][2] = w3 + 2 * WW;
    ga.bnp[0] = bn_q; ga.bnp[1] = bn_k; ga.bnp[2] = bn_v;
    ga.dst[0] = sqb; ga.dst[1] = skb; ga.dst[2] = svb;
    ga.mode[0] = 2; ga.mode[1] = 2; ga.mode[2] = 2;
    hmma_gemm<6><<<dim3(TBN / 128, 9), 256, GSMEM>>>(ga);

    attn_mma<<<T_ * B_ * H_, 256, ASMEM>>>(sqb, skb, svb, bm1, bm2, attn);

    attn_lif_pack<<<(BNROWS * C_ + 255) / 256, 256>>>(attn, aspk);

    // proj GEMM (binary A exact in bf16 -> 3 products) writes final spikes
    GArgs gp;
    gp.A[0] = aspk; gp.A[1] = aspk; gp.A[2] = aspk;
    gp.W[0][0] = w1 + 3 * WW; gp.W[0][1] = w2 + 3 * WW; gp.W[0][2] = w3 + 3 * WW;
    gp.W[1][0] = gp.W[0][0]; gp.W[1][1] = gp.W[0][1]; gp.W[1][2] = gp.W[0][2];
    gp.W[2][0] = gp.W[0][0]; gp.W[2][1] = gp.W[0][1]; gp.W[2][2] = gp.W[0][2];
    gp.bnp[0] = bn_p; gp.bnp[1] = bn_p; gp.bnp[2] = bn_p;
    gp.dst[0] = out; gp.dst[1] = out; gp.dst[2] = out;
    gp.mode[0] = 0; gp.mode[1] = 0; gp.mode[2] = 0;
    hmma_gemm<3><<<dim3(TBN / 128, 3), 256, GSMEM>>>(gp);
}